// round 5
// baseline (speedup 1.0000x reference)
#include <cuda_runtime.h>
#include <cuda_bf16.h>
#include <cstdint>
#include <cstddef>

#define S_LEN 2048
#define BATCH 4
#define DIM   1024
#define MQKV  (BATCH * S_LEN)   // 8192

// ---------------------------------------------------------------------------
// scratch (static device globals; no allocation in kernel_launch)
// ---------------------------------------------------------------------------
#define DEVBF(name, n) __device__ __align__(256) __nv_bfloat16 name[n]
DEVBF(g_xh,  (size_t)MQKV * DIM);
DEVBF(g_xl,  (size_t)MQKV * DIM);
DEVBF(g_wqh, (size_t)DIM * DIM);  DEVBF(g_wql, (size_t)DIM * DIM);
DEVBF(g_wkh, (size_t)DIM * DIM);  DEVBF(g_wkl, (size_t)DIM * DIM);
DEVBF(g_wvh, (size_t)DIM * DIM);  DEVBF(g_wvl, (size_t)DIM * DIM);
DEVBF(g_qh,  (size_t)MQKV * DIM); DEVBF(g_ql,  (size_t)MQKV * DIM);
DEVBF(g_kh,  (size_t)MQKV * DIM); DEVBF(g_kl,  (size_t)MQKV * DIM);
DEVBF(g_vh,  (size_t)MQKV * DIM); DEVBF(g_vl,  (size_t)MQKV * DIM);
DEVBF(g_vth, (size_t)MQKV * DIM); DEVBF(g_vtl, (size_t)MQKV * DIM);
DEVBF(g_ph,  (size_t)BATCH * S_LEN * S_LEN);
DEVBF(g_pl,  (size_t)BATCH * S_LEN * S_LEN);
__device__ __align__(256) float g_sc[(size_t)BATCH * S_LEN * S_LEN];

// ---------------------------------------------------------------------------
// PTX helpers — non-'a'-suffix ISA only (cp.async, ldmatrix, mma.sync).
// ---------------------------------------------------------------------------
__device__ __forceinline__ uint32_t smem_to_u32(const void* p) {
    uint32_t a;
    asm("{ .reg .u64 t; cvta.to.shared.u64 t, %1; cvt.u32.u64 %0, t; }"
        : "=r"(a) : "l"(p));
    return a;
}
__device__ __forceinline__ void cp_async16(uint32_t s, const void* g) {
    asm volatile("cp.async.cg.shared.global [%0], [%1], 16;" :: "r"(s), "l"(g));
}
#define CP_COMMIT() asm volatile("cp.async.commit_group;" ::: "memory")
#define CP_WAIT(n)  asm volatile("cp.async.wait_group %0;" :: "n"(n) : "memory")

__device__ __forceinline__ void ldsm_x4(uint32_t* r, uint32_t addr) {
    asm volatile("ldmatrix.sync.aligned.m8n8.x4.shared.b16 {%0,%1,%2,%3}, [%4];"
        : "=r"(r[0]), "=r"(r[1]), "=r"(r[2]), "=r"(r[3]) : "r"(addr));
}
__device__ __forceinline__ void mma16816(float* c, const uint32_t* a,
                                         uint32_t b0, uint32_t b1) {
    asm volatile(
        "mma.sync.aligned.m16n8k16.row.col.f32.bf16.bf16.f32 "
        "{%0,%1,%2,%3}, {%4,%5,%6,%7}, {%8,%9}, {%0,%1,%2,%3};"
        : "+f"(c[0]), "+f"(c[1]), "+f"(c[2]), "+f"(c[3])
        : "r"(a[0]), "r"(a[1]), "r"(a[2]), "r"(a[3]), "r"(b0), "r"(b1));
}

__device__ __forceinline__ void f2pair(float v, __nv_bfloat16& h, __nv_bfloat16& l) {
    h = __float2bfloat16(v);
    l = __float2bfloat16(v - __bfloat162float(h));
}

// ---------------------------------------------------------------------------
// NT GEMM, bf16 3-term fp32 emulation on tensor cores (hh + hl + lh).
// CTA tile 128x128, 512 threads, warp grid 4x4 (32x32 warp tiles), K-chunk 32,
// 3-stage cp.async pipeline, one __syncthreads per chunk.
// ---------------------------------------------------------------------------
#define ROW_B     80                 // 32 bf16 = 64B data + 16B pad
#define TILE_B    (128 * ROW_B)      // 10240 B
#define STAGE_B   (4 * TILE_B)       // Ah, Al, Bh, Bl = 40960 B
#define NSTAGE    3
#define GEMM_SMEM (NSTAGE * STAGE_B) // 122880 B

__global__ __launch_bounds__(512)
void gemm_bf3(const __nv_bfloat16* __restrict__ Ah, const __nv_bfloat16* __restrict__ Al,
              const __nv_bfloat16* __restrict__ Bh, const __nv_bfloat16* __restrict__ Bl,
              const float* __restrict__ bias,
              float* __restrict__ Cf,
              __nv_bfloat16* __restrict__ Ch, __nv_bfloat16* __restrict__ Cl,
              int M, int N, int K, float alpha,
              size_t sA, size_t sB, size_t sC)
{
    extern __shared__ __align__(16) char smem[];
    const uint32_t smem_u = smem_to_u32(smem);

    const int tid  = threadIdx.x;
    const int wid  = tid >> 5, lane = tid & 31;
    const int wm   = wid >> 2;        // 0..3 : warp row (32 rows)
    const int wn   = wid & 3;         // 0..3 : warp col (32 cols)
    const int m0   = blockIdx.y * 128;
    const int n0   = blockIdx.x * 128;

    Ah += sA * blockIdx.z; Al += sA * blockIdx.z;
    Bh += sB * blockIdx.z; Bl += sB * blockIdx.z;

    // ---- loader: 512 threads, 1 cp.async per tile per thread ----
    const int lrow = tid >> 2;         // 0..127
    const int lcol = tid & 3;          // 0..3 (16B chunk within 64B row)
    auto load_stage = [&](int c, int s) {
        const int k0 = c * 32;
        const uint32_t st = smem_u + s * STAGE_B + lrow * ROW_B + lcol * 16;
        const size_t goffA = (size_t)(m0 + lrow) * K + k0 + lcol * 8;
        const size_t goffB = (size_t)(n0 + lrow) * K + k0 + lcol * 8;
        cp_async16(st,              Ah + goffA);
        cp_async16(st + TILE_B,     Al + goffA);
        cp_async16(st + 2 * TILE_B, Bh + goffB);
        cp_async16(st + 3 * TILE_B, Bl + goffB);
        CP_COMMIT();
    };

    float acc[2][4][4];
    #pragma unroll
    for (int i = 0; i < 2; ++i)
        #pragma unroll
        for (int j = 0; j < 4; ++j)
            #pragma unroll
            for (int e = 0; e < 4; ++e) acc[i][j][e] = 0.f;

    // lane-derived ldmatrix offsets (within a stage)
    const uint32_t aoff = (uint32_t)((wm * 32 + (lane & 15)) * ROW_B +
                                     ((lane & 16) ? 16 : 0));
    const uint32_t boff = (uint32_t)((wn * 32 + ((lane & 16) >> 1) + (lane & 7)) * ROW_B +
                                     ((lane & 8) ? 16 : 0));

    const int NC = K >> 5;             // K / 32  (>= 32 for all our calls)
    load_stage(0, 0);
    load_stage(1, 1);

    int s = 0;                          // stage of chunk c
    for (int c = 0; c < NC; ++c) {
        if (c + 2 <= NC) { CP_WAIT(1); }   // stage c complete (1 group in flight)
        else             { CP_WAIT(0); }   // tail: drain all
        __syncthreads();

        if (c + 2 < NC) {
            int s2 = s + 2; if (s2 >= NSTAGE) s2 -= NSTAGE;
            load_stage(c + 2, s2);
        }

        const uint32_t st = smem_u + s * STAGE_B;
        #pragma unroll
        for (int kk = 0; kk < 2; ++kk) {    // two k16 steps per chunk
            const uint32_t kb = kk * 32;    // 16 bf16 = 32 B
            uint32_t ah[2][4], al[2][4], bh[2][4], bl[2][4];
            #pragma unroll
            for (int mi = 0; mi < 2; ++mi) {
                ldsm_x4(ah[mi], st + aoff + kb + mi * (16 * ROW_B));
                ldsm_x4(al[mi], st + TILE_B + aoff + kb + mi * (16 * ROW_B));
            }
            ldsm_x4(bh[0], st + 2 * TILE_B + boff + kb);
            ldsm_x4(bh[1], st + 2 * TILE_B + boff + kb + 16 * ROW_B);
            ldsm_x4(bl[0], st + 3 * TILE_B + boff + kb);
            ldsm_x4(bl[1], st + 3 * TILE_B + boff + kb + 16 * ROW_B);

            #pragma unroll
            for (int mi = 0; mi < 2; ++mi)
                #pragma unroll
                for (int nf = 0; nf < 4; ++nf) {
                    const int hsel = nf >> 1, p = (nf & 1) * 2;
                    mma16816(acc[mi][nf], ah[mi], bh[hsel][p], bh[hsel][p + 1]); // hh
                    mma16816(acc[mi][nf], ah[mi], bl[hsel][p], bl[hsel][p + 1]); // hl
                    mma16816(acc[mi][nf], al[mi], bh[hsel][p], bh[hsel][p + 1]); // lh
                }
        }
        if (++s == NSTAGE) s = 0;
    }

    // ---- epilogue ----
    const int r0 = lane >> 2;
    const int c0l = (lane & 3) * 2;
    #pragma unroll
    for (int mi = 0; mi < 2; ++mi) {
        #pragma unroll
        for (int nf = 0; nf < 4; ++nf) {
            const int col  = n0 + wn * 32 + nf * 8 + c0l;
            const int rowA = m0 + wm * 32 + mi * 16 + r0;
            float b0 = 0.f, b1 = 0.f;
            if (bias) { b0 = bias[col]; b1 = bias[col + 1]; }
            float v0 = fmaf(alpha, acc[mi][nf][0], b0);
            float v1 = fmaf(alpha, acc[mi][nf][1], b1);
            float v2 = fmaf(alpha, acc[mi][nf][2], b0);
            float v3 = fmaf(alpha, acc[mi][nf][3], b1);
            if (Cf) {
                float* p0 = Cf + sC * blockIdx.z + (size_t)rowA * N + col;
                *(float2*)p0                     = make_float2(v0, v1);
                *(float2*)(p0 + (size_t)8 * N)   = make_float2(v2, v3);
            }
            if (Ch) {
                size_t o0 = sC * blockIdx.z + (size_t)rowA * N + col;
                __nv_bfloat16 h0, l0, h1, l1;
                f2pair(v0, h0, l0); f2pair(v1, h1, l1);
                *(__nv_bfloat162*)(Ch + o0) = __nv_bfloat162(h0, h1);
                *(__nv_bfloat162*)(Cl + o0) = __nv_bfloat162(l0, l1);
                f2pair(v2, h0, l0); f2pair(v3, h1, l1);
                *(__nv_bfloat162*)(Ch + o0 + (size_t)8 * N) = __nv_bfloat162(h0, h1);
                *(__nv_bfloat162*)(Cl + o0 + (size_t)8 * N) = __nv_bfloat162(l0, l1);
            }
        }
    }
}

// ---------------------------------------------------------------------------
// x (S,B,D) fp32 -> xf (B,S,D) bf16 hi/lo
// ---------------------------------------------------------------------------
__global__ __launch_bounds__(256) void conv_x(const float* __restrict__ x,
                                              __nv_bfloat16* __restrict__ xh,
                                              __nv_bfloat16* __restrict__ xl) {
    int bs = blockIdx.x;
    int b = bs / S_LEN, s = bs % S_LEN;
    float4 v = ((const float4*)(x + ((size_t)s * BATCH + b) * DIM))[threadIdx.x];
    size_t o = (size_t)bs * DIM + (size_t)threadIdx.x * 4;
    __nv_bfloat16 h0,l0,h1,l1,h2,l2,h3,l3;
    f2pair(v.x, h0, l0); f2pair(v.y, h1, l1);
    f2pair(v.z, h2, l2); f2pair(v.w, h3, l3);
    ((__nv_bfloat162*)(xh + o))[0] = __nv_bfloat162(h0, h1);
    ((__nv_bfloat162*)(xh + o))[1] = __nv_bfloat162(h2, h3);
    ((__nv_bfloat162*)(xl + o))[0] = __nv_bfloat162(l0, l1);
    ((__nv_bfloat162*)(xl + o))[1] = __nv_bfloat162(l2, l3);
}

// fp32 array -> bf16 hi/lo (vectorized)
__global__ __launch_bounds__(256) void conv_pair(const float* __restrict__ X,
                                                 __nv_bfloat16* __restrict__ H,
                                                 __nv_bfloat16* __restrict__ L,
                                                 int n4) {
    int i = blockIdx.x * 256 + threadIdx.x;
    if (i >= n4) return;
    float4 v = ((const float4*)X)[i];
    size_t o = (size_t)i * 4;
    __nv_bfloat16 h0,l0,h1,l1,h2,l2,h3,l3;
    f2pair(v.x, h0, l0); f2pair(v.y, h1, l1);
    f2pair(v.z, h2, l2); f2pair(v.w, h3, l3);
    ((__nv_bfloat162*)(H + o))[0] = __nv_bfloat162(h0, h1);
    ((__nv_bfloat162*)(H + o))[1] = __nv_bfloat162(h2, h3);
    ((__nv_bfloat162*)(L + o))[0] = __nv_bfloat162(l0, l1);
    ((__nv_bfloat162*)(L + o))[1] = __nv_bfloat162(l2, l3);
}

// bf16 RxC -> CxR transpose (per batch z)
__global__ __launch_bounds__(256) void transpose_bf16(const __nv_bfloat16* __restrict__ in,
                                                      __nv_bfloat16* __restrict__ out,
                                                      int R, int C) {
    __shared__ __nv_bfloat16 t[32][33];
    in  += (size_t)blockIdx.z * R * C;
    out += (size_t)blockIdx.z * R * C;
    int c0 = blockIdx.x * 32, r0 = blockIdx.y * 32;
    #pragma unroll
    for (int i = threadIdx.y; i < 32; i += 8)
        t[i][threadIdx.x] = in[(size_t)(r0 + i) * C + c0 + threadIdx.x];
    __syncthreads();
    #pragma unroll
    for (int i = threadIdx.y; i < 32; i += 8)
        out[(size_t)(c0 + i) * R + r0 + threadIdx.x] = t[threadIdx.x][i];
}

// softmax over rows of sc (fp32, len S_LEN) -> bf16 hi/lo probs
__global__ __launch_bounds__(256) void softmax_conv(const float* __restrict__ sc,
                                                    __nv_bfloat16* __restrict__ ph,
                                                    __nv_bfloat16* __restrict__ pl) {
    const int tid = threadIdx.x;
    const float4* p4 = (const float4*)(sc + (size_t)blockIdx.x * S_LEN);
    __shared__ float red[8];

    float4 a = p4[tid], b = p4[tid + 256];
    float lmax = fmaxf(fmaxf(fmaxf(a.x, a.y), fmaxf(a.z, a.w)),
                       fmaxf(fmaxf(b.x, b.y), fmaxf(b.z, b.w)));
    #pragma unroll
    for (int o = 16; o; o >>= 1) lmax = fmaxf(lmax, __shfl_xor_sync(~0u, lmax, o));
    if ((tid & 31) == 0) red[tid >> 5] = lmax;
    __syncthreads();
    float gmax = red[0];
    #pragma unroll
    for (int w = 1; w < 8; ++w) gmax = fmaxf(gmax, red[w]);
    __syncthreads();

    float e[8];
    e[0] = __expf(a.x - gmax); e[1] = __expf(a.y - gmax);
    e[2] = __expf(a.z - gmax); e[3] = __expf(a.w - gmax);
    e[4] = __expf(b.x - gmax); e[5] = __expf(b.y - gmax);
    e[6] = __expf(b.z - gmax); e[7] = __expf(b.w - gmax);
    float lsum = ((e[0]+e[1]) + (e[2]+e[3])) + ((e[4]+e[5]) + (e[6]+e[7]));
    #pragma unroll
    for (int o = 16; o; o >>= 1) lsum += __shfl_xor_sync(~0u, lsum, o);
    if ((tid & 31) == 0) red[tid >> 5] = lsum;
    __syncthreads();
    float gsum = 0.f;
    #pragma unroll
    for (int w = 0; w < 8; ++w) gsum += red[w];
    float inv = 1.f / gsum;

    size_t o0 = (size_t)blockIdx.x * S_LEN + (size_t)tid * 4;
    #pragma unroll
    for (int half = 0; half < 2; ++half) {
        size_t o = o0 + half * 1024;
        __nv_bfloat16 h0,l0,h1,l1,h2,l2,h3,l3;
        f2pair(e[half*4+0] * inv, h0, l0);
        f2pair(e[half*4+1] * inv, h1, l1);
        f2pair(e[half*4+2] * inv, h2, l2);
        f2pair(e[half*4+3] * inv, h3, l3);
        ((__nv_bfloat162*)(ph + o))[0] = __nv_bfloat162(h0, h1);
        ((__nv_bfloat162*)(ph + o))[1] = __nv_bfloat162(h2, h3);
        ((__nv_bfloat162*)(pl + o))[0] = __nv_bfloat162(l0, l1);
        ((__nv_bfloat162*)(pl + o))[1] = __nv_bfloat162(l2, l3);
    }
}

// ---------------------------------------------------------------------------
extern "C" void kernel_launch(void* const* d_in, const int* in_sizes, int n_in,
                              void* d_out, int out_size) {
    const float* x  = (const float*)d_in[0];
    const float* Wq = (const float*)d_in[1];
    const float* bq = (const float*)d_in[2];
    const float* Wk = (const float*)d_in[3];
    const float* bk = (const float*)d_in[4];
    const float* Wv = (const float*)d_in[5];
    const float* bv = (const float*)d_in[6];
    float* out = (float*)d_out;

    cudaFuncSetAttribute(gemm_bf3, cudaFuncAttributeMaxDynamicSharedMemorySize,
                         GEMM_SMEM);

    __nv_bfloat16 *xh, *xl, *wqh, *wql, *wkh, *wkl, *wvh, *wvl;
    __nv_bfloat16 *qh, *ql, *kh, *kl, *vh, *vl, *vth, *vtl, *ph, *pl;
    float* sc;
    cudaGetSymbolAddress((void**)&xh, g_xh);   cudaGetSymbolAddress((void**)&xl, g_xl);
    cudaGetSymbolAddress((void**)&wqh, g_wqh); cudaGetSymbolAddress((void**)&wql, g_wql);
    cudaGetSymbolAddress((void**)&wkh, g_wkh); cudaGetSymbolAddress((void**)&wkl, g_wkl);
    cudaGetSymbolAddress((void**)&wvh, g_wvh); cudaGetSymbolAddress((void**)&wvl, g_wvl);
    cudaGetSymbolAddress((void**)&qh, g_qh);   cudaGetSymbolAddress((void**)&ql, g_ql);
    cudaGetSymbolAddress((void**)&kh, g_kh);   cudaGetSymbolAddress((void**)&kl, g_kl);
    cudaGetSymbolAddress((void**)&vh, g_vh);   cudaGetSymbolAddress((void**)&vl, g_vl);
    cudaGetSymbolAddress((void**)&vth, g_vth); cudaGetSymbolAddress((void**)&vtl, g_vtl);
    cudaGetSymbolAddress((void**)&ph, g_ph);   cudaGetSymbolAddress((void**)&pl, g_pl);
    cudaGetSymbolAddress((void**)&sc, g_sc);

    // 1) input conversions
    conv_x<<<MQKV, 256>>>(x, xh, xl);
    conv_pair<<<DIM * DIM / 4 / 256, 256>>>(Wq, wqh, wql, DIM * DIM / 4);
    conv_pair<<<DIM * DIM / 4 / 256, 256>>>(Wk, wkh, wkl, DIM * DIM / 4);
    conv_pair<<<DIM * DIM / 4 / 256, 256>>>(Wv, wvh, wvl, DIM * DIM / 4);

    // 2) QKV projections -> bf16 pairs directly (fused re-split epilogue)
    {
        dim3 grid(DIM / 128, MQKV / 128, 1);
        gemm_bf3<<<grid, 512, GEMM_SMEM>>>(xh, xl, wqh, wql, bq, nullptr, qh, ql,
                                           MQKV, DIM, DIM, 1.f, 0, 0, 0);
        gemm_bf3<<<grid, 512, GEMM_SMEM>>>(xh, xl, wkh, wkl, bk, nullptr, kh, kl,
                                           MQKV, DIM, DIM, 1.f, 0, 0, 0);
        gemm_bf3<<<grid, 512, GEMM_SMEM>>>(xh, xl, wvh, wvl, bv, nullptr, vh, vl,
                                           MQKV, DIM, DIM, 1.f, 0, 0, 0);
    }

    // 3) V -> V^T (per batch, [S,D] -> [D,S]) for K-major PV operand
    {
        dim3 grid(DIM / 32, S_LEN / 32, BATCH);
        dim3 blk(32, 8);
        transpose_bf16<<<grid, blk>>>(vh, vth, S_LEN, DIM);
        transpose_bf16<<<grid, blk>>>(vl, vtl, S_LEN, DIM);
    }

    // 4) scores = Q K^T / sqrt(D)  (fp32 out)
    {
        dim3 grid(S_LEN / 128, S_LEN / 128, BATCH);
        gemm_bf3<<<grid, 512, GEMM_SMEM>>>(qh, ql, kh, kl, nullptr, sc, nullptr, nullptr,
                                           S_LEN, S_LEN, DIM, 0.03125f,
                                           (size_t)S_LEN * DIM, (size_t)S_LEN * DIM,
                                           (size_t)S_LEN * S_LEN);
    }

    // 5) softmax -> bf16 prob pairs
    softmax_conv<<<BATCH * S_LEN, 256>>>(sc, ph, pl);

    // 6) out = P V  (fp32 straight into d_out; (B,S,D) flat == reshape)
    {
        dim3 grid(DIM / 128, S_LEN / 128, BATCH);
        gemm_bf3<<<grid, 512, GEMM_SMEM>>>(ph, pl, vth, vtl, nullptr, out, nullptr, nullptr,
                                           S_LEN, DIM, S_LEN, 1.f,
                                           (size_t)S_LEN * S_LEN, (size_t)S_LEN * DIM,
                                           (size_t)S_LEN * DIM);
    }
}

// round 6
// speedup vs baseline: 1.1479x; 1.1479x over previous
#include <cuda_runtime.h>
#include <cuda_bf16.h>
#include <cstdint>
#include <cstddef>

#define S_LEN 2048
#define BATCH 4
#define DIM   1024
#define MQKV  (BATCH * S_LEN)   // 8192

// ---------------------------------------------------------------------------
// scratch (static device globals; no allocation in kernel_launch)
// ---------------------------------------------------------------------------
#define DEVBF(name, n) __device__ __align__(256) __nv_bfloat16 name[n]
DEVBF(g_xh,  (size_t)MQKV * DIM);
DEVBF(g_xl,  (size_t)MQKV * DIM);
DEVBF(g_wqh, (size_t)DIM * DIM);  DEVBF(g_wql, (size_t)DIM * DIM);
DEVBF(g_wkh, (size_t)DIM * DIM);  DEVBF(g_wkl, (size_t)DIM * DIM);
DEVBF(g_wvh, (size_t)DIM * DIM);  DEVBF(g_wvl, (size_t)DIM * DIM);
DEVBF(g_qh,  (size_t)MQKV * DIM); DEVBF(g_ql,  (size_t)MQKV * DIM);
DEVBF(g_kh,  (size_t)MQKV * DIM); DEVBF(g_kl,  (size_t)MQKV * DIM);
DEVBF(g_vh,  (size_t)MQKV * DIM); DEVBF(g_vl,  (size_t)MQKV * DIM);
DEVBF(g_vth, (size_t)MQKV * DIM); DEVBF(g_vtl, (size_t)MQKV * DIM);
DEVBF(g_ph,  (size_t)BATCH * S_LEN * S_LEN);
DEVBF(g_pl,  (size_t)BATCH * S_LEN * S_LEN);
__device__ __align__(256) float g_sc[(size_t)BATCH * S_LEN * S_LEN];

// ---------------------------------------------------------------------------
// PTX helpers — non-'a'-suffix ISA only (cp.async, ldmatrix, mma.sync).
// ---------------------------------------------------------------------------
__device__ __forceinline__ uint32_t smem_to_u32(const void* p) {
    uint32_t a;
    asm("{ .reg .u64 t; cvta.to.shared.u64 t, %1; cvt.u32.u64 %0, t; }"
        : "=r"(a) : "l"(p));
    return a;
}
__device__ __forceinline__ void cp_async16(uint32_t s, const void* g) {
    asm volatile("cp.async.cg.shared.global [%0], [%1], 16;" :: "r"(s), "l"(g));
}
#define CP_COMMIT() asm volatile("cp.async.commit_group;" ::: "memory")
#define CP_WAIT(n)  asm volatile("cp.async.wait_group %0;" :: "n"(n) : "memory")

__device__ __forceinline__ void ldsm_x4(uint32_t* r, uint32_t addr) {
    asm volatile("ldmatrix.sync.aligned.m8n8.x4.shared.b16 {%0,%1,%2,%3}, [%4];"
        : "=r"(r[0]), "=r"(r[1]), "=r"(r[2]), "=r"(r[3]) : "r"(addr));
}
__device__ __forceinline__ void mma16816(float* c, const uint32_t* a,
                                         uint32_t b0, uint32_t b1) {
    asm volatile(
        "mma.sync.aligned.m16n8k16.row.col.f32.bf16.bf16.f32 "
        "{%0,%1,%2,%3}, {%4,%5,%6,%7}, {%8,%9}, {%0,%1,%2,%3};"
        : "+f"(c[0]), "+f"(c[1]), "+f"(c[2]), "+f"(c[3])
        : "r"(a[0]), "r"(a[1]), "r"(a[2]), "r"(a[3]), "r"(b0), "r"(b1));
}

__device__ __forceinline__ void f2pair(float v, __nv_bfloat16& h, __nv_bfloat16& l) {
    h = __float2bfloat16(v);
    l = __float2bfloat16(v - __bfloat162float(h));
}

// ---------------------------------------------------------------------------
// NT GEMM, bf16 3-term fp32 emulation on tensor cores (hh + hl + lh).
// CTA tile 128x128, 256 threads, 8 warps (2x4) of 64x32 warp tiles, K-chunk 32,
// cp.async double buffer. MMA issue order is term-major: 16 independent
// accumulators between successive writes to the same acc tile (hides HMMA
// latency at low warps/SMSP). Per-acc FP order stays hh,hl,lh.
// ---------------------------------------------------------------------------
#define ROW_B     80                 // 32 bf16 = 64B data + 16B pad
#define TILE_B    (128 * ROW_B)      // 10240 B
#define STAGE_B   (4 * TILE_B)       // Ah, Al, Bh, Bl
#define GEMM_SMEM (2 * STAGE_B)      // 81920 B

__global__ __launch_bounds__(256)
void gemm_bf3(const __nv_bfloat16* __restrict__ Ah, const __nv_bfloat16* __restrict__ Al,
              const __nv_bfloat16* __restrict__ Bh, const __nv_bfloat16* __restrict__ Bl,
              const float* __restrict__ bias,
              float* __restrict__ Cf,
              __nv_bfloat16* __restrict__ Ch, __nv_bfloat16* __restrict__ Cl,
              int M, int N, int K, float alpha,
              size_t sA, size_t sB, size_t sC)
{
    extern __shared__ __align__(16) char smem[];
    const uint32_t smem_u = smem_to_u32(smem);

    const int tid  = threadIdx.x;
    const int wid  = tid >> 5, lane = tid & 31;
    const int wm   = wid >> 2;        // 0..1 : warp row (64 rows each)
    const int wn   = wid & 3;         // 0..3 : warp col (32 cols each)
    const int m0   = blockIdx.y * 128;
    const int n0   = blockIdx.x * 128;

    Ah += sA * blockIdx.z; Al += sA * blockIdx.z;
    Bh += sB * blockIdx.z; Bl += sB * blockIdx.z;

    // ---- loader: 4 tiles x 512 16B-chunks, 2 chunks per thread per tile ----
    const int ci0 = tid;               // chunk ids: tid, tid+256
    auto load_stage = [&](int c, int s) {
        const int k0 = c * 32;
        const uint32_t st = smem_u + s * STAGE_B;
        const __nv_bfloat16* gsrc[4] = { Ah, Al, Bh, Bl };
        const int rb[4] = { m0, m0, n0, n0 };
        #pragma unroll
        for (int t = 0; t < 4; ++t) {
            #pragma unroll
            for (int h = 0; h < 2; ++h) {
                int ci  = ci0 + h * 256;
                int row = ci >> 2, col = ci & 3;
                const void* g = gsrc[t] + (size_t)(rb[t] + row) * K + k0 + col * 8;
                cp_async16(st + t * TILE_B + row * ROW_B + col * 16, g);
            }
        }
        CP_COMMIT();
    };

    float acc[4][4][4];
    #pragma unroll
    for (int i = 0; i < 4; ++i)
        #pragma unroll
        for (int j = 0; j < 4; ++j)
            #pragma unroll
            for (int e = 0; e < 4; ++e) acc[i][j][e] = 0.f;

    const int NC = K >> 5;             // K / 32
    load_stage(0, 0);

    for (int c = 0; c < NC; ++c) {
        if (c + 1 < NC) { load_stage(c + 1, (c + 1) & 1); CP_WAIT(1); }
        else            { CP_WAIT(0); }
        __syncthreads();

        const uint32_t st = smem_u + (c & 1) * STAGE_B;
        // lane-derived ldmatrix addresses
        const uint32_t aoff = (uint32_t)((wm * 64 + (lane & 15)) * ROW_B +
                                         ((lane & 16) ? 16 : 0));
        const uint32_t boff = (uint32_t)((wn * 32 + ((lane & 16) >> 1) + (lane & 7)) * ROW_B +
                                         ((lane & 8) ? 16 : 0));
        #pragma unroll
        for (int kk = 0; kk < 2; ++kk) {    // two k16 steps per chunk
            const uint32_t kb = kk * 32;    // 16 bf16 = 32 B
            uint32_t ah[4][4], al[4][4], bh[2][4], bl[2][4];
            #pragma unroll
            for (int mi = 0; mi < 4; ++mi) {
                ldsm_x4(ah[mi], st + aoff + kb + mi * (16 * ROW_B));
                ldsm_x4(al[mi], st + TILE_B + aoff + kb + mi * (16 * ROW_B));
            }
            ldsm_x4(bh[0], st + 2 * TILE_B + boff + kb);
            ldsm_x4(bh[1], st + 2 * TILE_B + boff + kb + 16 * ROW_B);
            ldsm_x4(bl[0], st + 3 * TILE_B + boff + kb);
            ldsm_x4(bl[1], st + 3 * TILE_B + boff + kb + 16 * ROW_B);

            // term-major issue: 16 independent accumulators between reuses
            #pragma unroll
            for (int mi = 0; mi < 4; ++mi)
                #pragma unroll
                for (int nf = 0; nf < 4; ++nf) {
                    const int hsel = nf >> 1, p = (nf & 1) * 2;
                    mma16816(acc[mi][nf], ah[mi], bh[hsel][p], bh[hsel][p + 1]); // hh
                }
            #pragma unroll
            for (int mi = 0; mi < 4; ++mi)
                #pragma unroll
                for (int nf = 0; nf < 4; ++nf) {
                    const int hsel = nf >> 1, p = (nf & 1) * 2;
                    mma16816(acc[mi][nf], ah[mi], bl[hsel][p], bl[hsel][p + 1]); // hl
                }
            #pragma unroll
            for (int mi = 0; mi < 4; ++mi)
                #pragma unroll
                for (int nf = 0; nf < 4; ++nf) {
                    const int hsel = nf >> 1, p = (nf & 1) * 2;
                    mma16816(acc[mi][nf], al[mi], bh[hsel][p], bh[hsel][p + 1]); // lh
                }
        }
        __syncthreads();
    }

    // ---- epilogue ----
    const int r0 = lane >> 2;
    const int c0l = (lane & 3) * 2;
    #pragma unroll
    for (int mi = 0; mi < 4; ++mi) {
        #pragma unroll
        for (int nf = 0; nf < 4; ++nf) {
            const int col  = n0 + wn * 32 + nf * 8 + c0l;
            const int rowA = m0 + wm * 64 + mi * 16 + r0;
            float b0 = 0.f, b1 = 0.f;
            if (bias) { b0 = bias[col]; b1 = bias[col + 1]; }
            float v0 = fmaf(alpha, acc[mi][nf][0], b0);
            float v1 = fmaf(alpha, acc[mi][nf][1], b1);
            float v2 = fmaf(alpha, acc[mi][nf][2], b0);
            float v3 = fmaf(alpha, acc[mi][nf][3], b1);
            if (Cf) {
                float* p0 = Cf + sC * blockIdx.z + (size_t)rowA * N + col;
                *(float2*)p0                     = make_float2(v0, v1);
                *(float2*)(p0 + (size_t)8 * N)   = make_float2(v2, v3);
            }
            if (Ch) {
                size_t o0 = sC * blockIdx.z + (size_t)rowA * N + col;
                __nv_bfloat16 h0, l0, h1, l1;
                f2pair(v0, h0, l0); f2pair(v1, h1, l1);
                *(__nv_bfloat162*)(Ch + o0) = __nv_bfloat162(h0, h1);
                *(__nv_bfloat162*)(Cl + o0) = __nv_bfloat162(l0, l1);
                f2pair(v2, h0, l0); f2pair(v3, h1, l1);
                *(__nv_bfloat162*)(Ch + o0 + (size_t)8 * N) = __nv_bfloat162(h0, h1);
                *(__nv_bfloat162*)(Cl + o0 + (size_t)8 * N) = __nv_bfloat162(l0, l1);
            }
        }
    }
}

// ---------------------------------------------------------------------------
// x (S,B,D) fp32 -> xf (B,S,D) bf16 hi/lo
// ---------------------------------------------------------------------------
__global__ __launch_bounds__(256) void conv_x(const float* __restrict__ x,
                                              __nv_bfloat16* __restrict__ xh,
                                              __nv_bfloat16* __restrict__ xl) {
    int bs = blockIdx.x;
    int b = bs / S_LEN, s = bs % S_LEN;
    float4 v = ((const float4*)(x + ((size_t)s * BATCH + b) * DIM))[threadIdx.x];
    size_t o = (size_t)bs * DIM + (size_t)threadIdx.x * 4;
    __nv_bfloat16 h0,l0,h1,l1,h2,l2,h3,l3;
    f2pair(v.x, h0, l0); f2pair(v.y, h1, l1);
    f2pair(v.z, h2, l2); f2pair(v.w, h3, l3);
    ((__nv_bfloat162*)(xh + o))[0] = __nv_bfloat162(h0, h1);
    ((__nv_bfloat162*)(xh + o))[1] = __nv_bfloat162(h2, h3);
    ((__nv_bfloat162*)(xl + o))[0] = __nv_bfloat162(l0, l1);
    ((__nv_bfloat162*)(xl + o))[1] = __nv_bfloat162(l2, l3);
}

// fp32 array -> bf16 hi/lo (vectorized)
__global__ __launch_bounds__(256) void conv_pair(const float* __restrict__ X,
                                                 __nv_bfloat16* __restrict__ H,
                                                 __nv_bfloat16* __restrict__ L,
                                                 int n4) {
    int i = blockIdx.x * 256 + threadIdx.x;
    if (i >= n4) return;
    float4 v = ((const float4*)X)[i];
    size_t o = (size_t)i * 4;
    __nv_bfloat16 h0,l0,h1,l1,h2,l2,h3,l3;
    f2pair(v.x, h0, l0); f2pair(v.y, h1, l1);
    f2pair(v.z, h2, l2); f2pair(v.w, h3, l3);
    ((__nv_bfloat162*)(H + o))[0] = __nv_bfloat162(h0, h1);
    ((__nv_bfloat162*)(H + o))[1] = __nv_bfloat162(h2, h3);
    ((__nv_bfloat162*)(L + o))[0] = __nv_bfloat162(l0, l1);
    ((__nv_bfloat162*)(L + o))[1] = __nv_bfloat162(l2, l3);
}

// bf16 RxC -> CxR transpose (per batch z)
__global__ __launch_bounds__(256) void transpose_bf16(const __nv_bfloat16* __restrict__ in,
                                                      __nv_bfloat16* __restrict__ out,
                                                      int R, int C) {
    __shared__ __nv_bfloat16 t[32][33];
    in  += (size_t)blockIdx.z * R * C;
    out += (size_t)blockIdx.z * R * C;
    int c0 = blockIdx.x * 32, r0 = blockIdx.y * 32;
    #pragma unroll
    for (int i = threadIdx.y; i < 32; i += 8)
        t[i][threadIdx.x] = in[(size_t)(r0 + i) * C + c0 + threadIdx.x];
    __syncthreads();
    #pragma unroll
    for (int i = threadIdx.y; i < 32; i += 8)
        out[(size_t)(c0 + i) * R + r0 + threadIdx.x] = t[threadIdx.x][i];
}

// softmax over rows of sc (fp32, len S_LEN) -> bf16 hi/lo probs
__global__ __launch_bounds__(256) void softmax_conv(const float* __restrict__ sc,
                                                    __nv_bfloat16* __restrict__ ph,
                                                    __nv_bfloat16* __restrict__ pl) {
    const int tid = threadIdx.x;
    const float4* p4 = (const float4*)(sc + (size_t)blockIdx.x * S_LEN);
    __shared__ float red[8];

    float4 a = p4[tid], b = p4[tid + 256];
    float lmax = fmaxf(fmaxf(fmaxf(a.x, a.y), fmaxf(a.z, a.w)),
                       fmaxf(fmaxf(b.x, b.y), fmaxf(b.z, b.w)));
    #pragma unroll
    for (int o = 16; o; o >>= 1) lmax = fmaxf(lmax, __shfl_xor_sync(~0u, lmax, o));
    if ((tid & 31) == 0) red[tid >> 5] = lmax;
    __syncthreads();
    float gmax = red[0];
    #pragma unroll
    for (int w = 1; w < 8; ++w) gmax = fmaxf(gmax, red[w]);
    __syncthreads();

    float e[8];
    e[0] = __expf(a.x - gmax); e[1] = __expf(a.y - gmax);
    e[2] = __expf(a.z - gmax); e[3] = __expf(a.w - gmax);
    e[4] = __expf(b.x - gmax); e[5] = __expf(b.y - gmax);
    e[6] = __expf(b.z - gmax); e[7] = __expf(b.w - gmax);
    float lsum = ((e[0]+e[1]) + (e[2]+e[3])) + ((e[4]+e[5]) + (e[6]+e[7]));
    #pragma unroll
    for (int o = 16; o; o >>= 1) lsum += __shfl_xor_sync(~0u, lsum, o);
    if ((tid & 31) == 0) red[tid >> 5] = lsum;
    __syncthreads();
    float gsum = 0.f;
    #pragma unroll
    for (int w = 0; w < 8; ++w) gsum += red[w];
    float inv = 1.f / gsum;

    size_t o0 = (size_t)blockIdx.x * S_LEN + (size_t)tid * 4;
    #pragma unroll
    for (int half = 0; half < 2; ++half) {
        size_t o = o0 + half * 1024;
        __nv_bfloat16 h0,l0,h1,l1,h2,l2,h3,l3;
        f2pair(e[half*4+0] * inv, h0, l0);
        f2pair(e[half*4+1] * inv, h1, l1);
        f2pair(e[half*4+2] * inv, h2, l2);
        f2pair(e[half*4+3] * inv, h3, l3);
        ((__nv_bfloat162*)(ph + o))[0] = __nv_bfloat162(h0, h1);
        ((__nv_bfloat162*)(ph + o))[1] = __nv_bfloat162(h2, h3);
        ((__nv_bfloat162*)(pl + o))[0] = __nv_bfloat162(l0, l1);
        ((__nv_bfloat162*)(pl + o))[1] = __nv_bfloat162(l2, l3);
    }
}

// ---------------------------------------------------------------------------
extern "C" void kernel_launch(void* const* d_in, const int* in_sizes, int n_in,
                              void* d_out, int out_size) {
    const float* x  = (const float*)d_in[0];
    const float* Wq = (const float*)d_in[1];
    const float* bq = (const float*)d_in[2];
    const float* Wk = (const float*)d_in[3];
    const float* bk = (const float*)d_in[4];
    const float* Wv = (const float*)d_in[5];
    const float* bv = (const float*)d_in[6];
    float* out = (float*)d_out;

    cudaFuncSetAttribute(gemm_bf3, cudaFuncAttributeMaxDynamicSharedMemorySize,
                         GEMM_SMEM);

    __nv_bfloat16 *xh, *xl, *wqh, *wql, *wkh, *wkl, *wvh, *wvl;
    __nv_bfloat16 *qh, *ql, *kh, *kl, *vh, *vl, *vth, *vtl, *ph, *pl;
    float* sc;
    cudaGetSymbolAddress((void**)&xh, g_xh);   cudaGetSymbolAddress((void**)&xl, g_xl);
    cudaGetSymbolAddress((void**)&wqh, g_wqh); cudaGetSymbolAddress((void**)&wql, g_wql);
    cudaGetSymbolAddress((void**)&wkh, g_wkh); cudaGetSymbolAddress((void**)&wkl, g_wkl);
    cudaGetSymbolAddress((void**)&wvh, g_wvh); cudaGetSymbolAddress((void**)&wvl, g_wvl);
    cudaGetSymbolAddress((void**)&qh, g_qh);   cudaGetSymbolAddress((void**)&ql, g_ql);
    cudaGetSymbolAddress((void**)&kh, g_kh);   cudaGetSymbolAddress((void**)&kl, g_kl);
    cudaGetSymbolAddress((void**)&vh, g_vh);   cudaGetSymbolAddress((void**)&vl, g_vl);
    cudaGetSymbolAddress((void**)&vth, g_vth); cudaGetSymbolAddress((void**)&vtl, g_vtl);
    cudaGetSymbolAddress((void**)&ph, g_ph);   cudaGetSymbolAddress((void**)&pl, g_pl);
    cudaGetSymbolAddress((void**)&sc, g_sc);

    // 1) input conversions
    conv_x<<<MQKV, 256>>>(x, xh, xl);
    conv_pair<<<DIM * DIM / 4 / 256, 256>>>(Wq, wqh, wql, DIM * DIM / 4);
    conv_pair<<<DIM * DIM / 4 / 256, 256>>>(Wk, wkh, wkl, DIM * DIM / 4);
    conv_pair<<<DIM * DIM / 4 / 256, 256>>>(Wv, wvh, wvl, DIM * DIM / 4);

    // 2) QKV projections -> bf16 pairs directly (fused re-split epilogue)
    {
        dim3 grid(DIM / 128, MQKV / 128, 1);
        gemm_bf3<<<grid, 256, GEMM_SMEM>>>(xh, xl, wqh, wql, bq, nullptr, qh, ql,
                                           MQKV, DIM, DIM, 1.f, 0, 0, 0);
        gemm_bf3<<<grid, 256, GEMM_SMEM>>>(xh, xl, wkh, wkl, bk, nullptr, kh, kl,
                                           MQKV, DIM, DIM, 1.f, 0, 0, 0);
        gemm_bf3<<<grid, 256, GEMM_SMEM>>>(xh, xl, wvh, wvl, bv, nullptr, vh, vl,
                                           MQKV, DIM, DIM, 1.f, 0, 0, 0);
    }

    // 3) V -> V^T (per batch, [S,D] -> [D,S]) for K-major PV operand
    {
        dim3 grid(DIM / 32, S_LEN / 32, BATCH);
        dim3 blk(32, 8);
        transpose_bf16<<<grid, blk>>>(vh, vth, S_LEN, DIM);
        transpose_bf16<<<grid, blk>>>(vl, vtl, S_LEN, DIM);
    }

    // 4) scores = Q K^T / sqrt(D)  (fp32 out)
    {
        dim3 grid(S_LEN / 128, S_LEN / 128, BATCH);
        gemm_bf3<<<grid, 256, GEMM_SMEM>>>(qh, ql, kh, kl, nullptr, sc, nullptr, nullptr,
                                           S_LEN, S_LEN, DIM, 0.03125f,
                                           (size_t)S_LEN * DIM, (size_t)S_LEN * DIM,
                                           (size_t)S_LEN * S_LEN);
    }

    // 5) softmax -> bf16 prob pairs
    softmax_conv<<<BATCH * S_LEN, 256>>>(sc, ph, pl);

    // 6) out = P V  (fp32 straight into d_out; (B,S,D) flat == reshape)
    {
        dim3 grid(DIM / 128, S_LEN / 128, BATCH);
        gemm_bf3<<<grid, 256, GEMM_SMEM>>>(ph, pl, vth, vtl, nullptr, out, nullptr, nullptr,
                                           S_LEN, DIM, S_LEN, 1.f,
                                           (size_t)S_LEN * S_LEN, (size_t)S_LEN * DIM,
                                           (size_t)S_LEN * DIM);
    }
}

// round 7
// speedup vs baseline: 1.3147x; 1.1454x over previous
#include <cuda_runtime.h>
#include <cuda_fp16.h>
#include <cstdint>
#include <cstddef>

#define S_LEN 2048
#define BATCH 4
#define DIM   1024
#define MQKV  (BATCH * S_LEN)   // 8192

// ---------------------------------------------------------------------------
// scratch (static device globals; no allocation in kernel_launch)
// ---------------------------------------------------------------------------
#define DEVH(name, n) __device__ __align__(256) __half name[n]
DEVH(g_xh,  (size_t)MQKV * DIM);
DEVH(g_xl,  (size_t)MQKV * DIM);
DEVH(g_wqh, (size_t)DIM * DIM);  DEVH(g_wql, (size_t)DIM * DIM);
DEVH(g_wkh, (size_t)DIM * DIM);  DEVH(g_wkl, (size_t)DIM * DIM);
DEVH(g_wvh, (size_t)DIM * DIM);  DEVH(g_wvl, (size_t)DIM * DIM);
DEVH(g_qh,  (size_t)MQKV * DIM); DEVH(g_ql,  (size_t)MQKV * DIM);
DEVH(g_kh,  (size_t)MQKV * DIM); DEVH(g_kl,  (size_t)MQKV * DIM);
DEVH(g_vh,  (size_t)MQKV * DIM); DEVH(g_vl,  (size_t)MQKV * DIM);
DEVH(g_vth, (size_t)MQKV * DIM); DEVH(g_vtl, (size_t)MQKV * DIM);
DEVH(g_ph,  (size_t)BATCH * S_LEN * S_LEN);
DEVH(g_pl,  (size_t)BATCH * S_LEN * S_LEN);
__device__ __align__(256) float g_sc[(size_t)BATCH * S_LEN * S_LEN];

// ---------------------------------------------------------------------------
// PTX helpers — non-'a'-suffix ISA only (cp.async, ldmatrix, mma.sync).
// ---------------------------------------------------------------------------
__device__ __forceinline__ uint32_t smem_to_u32(const void* p) {
    uint32_t a;
    asm("{ .reg .u64 t; cvta.to.shared.u64 t, %1; cvt.u32.u64 %0, t; }"
        : "=r"(a) : "l"(p));
    return a;
}
__device__ __forceinline__ void cp_async16(uint32_t s, const void* g) {
    asm volatile("cp.async.cg.shared.global [%0], [%1], 16;" :: "r"(s), "l"(g));
}
#define CP_COMMIT() asm volatile("cp.async.commit_group;" ::: "memory")
#define CP_WAIT(n)  asm volatile("cp.async.wait_group %0;" :: "n"(n) : "memory")

__device__ __forceinline__ void ldsm_x4(uint32_t* r, uint32_t addr) {
    asm volatile("ldmatrix.sync.aligned.m8n8.x4.shared.b16 {%0,%1,%2,%3}, [%4];"
        : "=r"(r[0]), "=r"(r[1]), "=r"(r[2]), "=r"(r[3]) : "r"(addr));
}
__device__ __forceinline__ void mma16816(float* c, const uint32_t* a,
                                         uint32_t b0, uint32_t b1) {
    asm volatile(
        "mma.sync.aligned.m16n8k16.row.col.f32.f16.f16.f32 "
        "{%0,%1,%2,%3}, {%4,%5,%6,%7}, {%8,%9}, {%0,%1,%2,%3};"
        : "+f"(c[0]), "+f"(c[1]), "+f"(c[2]), "+f"(c[3])
        : "r"(a[0]), "r"(a[1]), "r"(a[2]), "r"(a[3]), "r"(b0), "r"(b1));
}

__device__ __forceinline__ void f2pair(float v, __half& h, __half& l) {
    h = __float2half_rn(v);
    l = __float2half_rn(v - __half2float(h));
}

// ---------------------------------------------------------------------------
// NT GEMM, fp16 split fp32 emulation on tensor cores.
//   NTERMS=3:  hh + lh + hl   (needs Ah,Al,Bh,Bl)   residual ~2^-24
//   NTERMS=2:  hh + lh        (needs Ah,Al,Bh)      residual ~2^-12
// CTA tile 128x128, 256 threads, 8 warps (2x4) of 64x32 warp tiles, K-chunk 32,
// cp.async double buffer, term-major MMA issue.
// ---------------------------------------------------------------------------
#define ROW_B     80                 // 32 fp16 = 64B data + 16B pad
#define TILE_B    (128 * ROW_B)      // 10240 B
#define STAGE_B   (4 * TILE_B)       // Ah, Al, Bh, (Bl)
#define GEMM_SMEM (2 * STAGE_B)      // 81920 B

template <int NTERMS>
__global__ __launch_bounds__(256)
void gemm_fp16s(const __half* __restrict__ Ah, const __half* __restrict__ Al,
                const __half* __restrict__ Bh, const __half* __restrict__ Bl,
                const float* __restrict__ bias,
                float* __restrict__ Cf,
                __half* __restrict__ Ch, __half* __restrict__ Cl,
                int M, int N, int K, float alpha,
                size_t sA, size_t sB, size_t sC)
{
    extern __shared__ __align__(16) char smem[];
    const uint32_t smem_u = smem_to_u32(smem);

    const int tid  = threadIdx.x;
    const int wid  = tid >> 5, lane = tid & 31;
    const int wm   = wid >> 2;        // 0..1 : warp row (64 rows each)
    const int wn   = wid & 3;         // 0..3 : warp col (32 cols each)
    const int m0   = blockIdx.y * 128;
    const int n0   = blockIdx.x * 128;

    Ah += sA * blockIdx.z; Al += sA * blockIdx.z;
    Bh += sB * blockIdx.z;
    if (NTERMS == 3) Bl += sB * blockIdx.z;

    const int NT = (NTERMS == 3) ? 4 : 3;   // tiles per stage actually loaded

    // ---- loader: NT tiles x 512 16B-chunks, 2 chunks per thread per tile ----
    const int ci0 = tid;               // chunk ids: tid, tid+256
    auto load_stage = [&](int c, int s) {
        const int k0 = c * 32;
        const uint32_t st = smem_u + s * STAGE_B;
        const __half* gsrc[4] = { Ah, Al, Bh, Bl };
        const int rb[4] = { m0, m0, n0, n0 };
        #pragma unroll
        for (int t = 0; t < NT; ++t) {
            #pragma unroll
            for (int h = 0; h < 2; ++h) {
                int ci  = ci0 + h * 256;
                int row = ci >> 2, col = ci & 3;
                const void* g = gsrc[t] + (size_t)(rb[t] + row) * K + k0 + col * 8;
                cp_async16(st + t * TILE_B + row * ROW_B + col * 16, g);
            }
        }
        CP_COMMIT();
    };

    float acc[4][4][4];
    #pragma unroll
    for (int i = 0; i < 4; ++i)
        #pragma unroll
        for (int j = 0; j < 4; ++j)
            #pragma unroll
            for (int e = 0; e < 4; ++e) acc[i][j][e] = 0.f;

    const int NC = K >> 5;             // K / 32
    load_stage(0, 0);

    for (int c = 0; c < NC; ++c) {
        if (c + 1 < NC) { load_stage(c + 1, (c + 1) & 1); CP_WAIT(1); }
        else            { CP_WAIT(0); }
        __syncthreads();

        const uint32_t st = smem_u + (c & 1) * STAGE_B;
        const uint32_t aoff = (uint32_t)((wm * 64 + (lane & 15)) * ROW_B +
                                         ((lane & 16) ? 16 : 0));
        const uint32_t boff = (uint32_t)((wn * 32 + ((lane & 16) >> 1) + (lane & 7)) * ROW_B +
                                         ((lane & 8) ? 16 : 0));
        #pragma unroll
        for (int kk = 0; kk < 2; ++kk) {    // two k16 steps per chunk
            const uint32_t kb = kk * 32;    // 16 fp16 = 32 B
            uint32_t ah[4][4], al[4][4], bh[2][4], bl[2][4];
            #pragma unroll
            for (int mi = 0; mi < 4; ++mi) {
                ldsm_x4(ah[mi], st + aoff + kb + mi * (16 * ROW_B));
                ldsm_x4(al[mi], st + TILE_B + aoff + kb + mi * (16 * ROW_B));
            }
            ldsm_x4(bh[0], st + 2 * TILE_B + boff + kb);
            ldsm_x4(bh[1], st + 2 * TILE_B + boff + kb + 16 * ROW_B);
            if (NTERMS == 3) {
                ldsm_x4(bl[0], st + 3 * TILE_B + boff + kb);
                ldsm_x4(bl[1], st + 3 * TILE_B + boff + kb + 16 * ROW_B);
            }

            // term-major issue: 16 independent accumulators between reuses
            #pragma unroll
            for (int mi = 0; mi < 4; ++mi)
                #pragma unroll
                for (int nf = 0; nf < 4; ++nf) {
                    const int hsel = nf >> 1, p = (nf & 1) * 2;
                    mma16816(acc[mi][nf], ah[mi], bh[hsel][p], bh[hsel][p + 1]); // hh
                }
            #pragma unroll
            for (int mi = 0; mi < 4; ++mi)
                #pragma unroll
                for (int nf = 0; nf < 4; ++nf) {
                    const int hsel = nf >> 1, p = (nf & 1) * 2;
                    mma16816(acc[mi][nf], al[mi], bh[hsel][p], bh[hsel][p + 1]); // lh
                }
            if (NTERMS == 3) {
                #pragma unroll
                for (int mi = 0; mi < 4; ++mi)
                    #pragma unroll
                    for (int nf = 0; nf < 4; ++nf) {
                        const int hsel = nf >> 1, p = (nf & 1) * 2;
                        mma16816(acc[mi][nf], ah[mi], bl[hsel][p], bl[hsel][p + 1]); // hl
                    }
            }
        }
        __syncthreads();
    }

    // ---- epilogue ----
    const int r0 = lane >> 2;
    const int c0l = (lane & 3) * 2;
    #pragma unroll
    for (int mi = 0; mi < 4; ++mi) {
        #pragma unroll
        for (int nf = 0; nf < 4; ++nf) {
            const int col  = n0 + wn * 32 + nf * 8 + c0l;
            const int rowA = m0 + wm * 64 + mi * 16 + r0;
            float b0 = 0.f, b1 = 0.f;
            if (bias) { b0 = bias[col]; b1 = bias[col + 1]; }
            float v0 = fmaf(alpha, acc[mi][nf][0], b0);
            float v1 = fmaf(alpha, acc[mi][nf][1], b1);
            float v2 = fmaf(alpha, acc[mi][nf][2], b0);
            float v3 = fmaf(alpha, acc[mi][nf][3], b1);
            if (Cf) {
                float* p0 = Cf + sC * blockIdx.z + (size_t)rowA * N + col;
                *(float2*)p0                     = make_float2(v0, v1);
                *(float2*)(p0 + (size_t)8 * N)   = make_float2(v2, v3);
            }
            if (Ch) {
                size_t o0 = sC * blockIdx.z + (size_t)rowA * N + col;
                __half h0, l0, h1, l1;
                f2pair(v0, h0, l0); f2pair(v1, h1, l1);
                *(__half2*)(Ch + o0) = __halves2half2(h0, h1);
                *(__half2*)(Cl + o0) = __halves2half2(l0, l1);
                f2pair(v2, h0, l0); f2pair(v3, h1, l1);
                *(__half2*)(Ch + o0 + (size_t)8 * N) = __halves2half2(h0, h1);
                *(__half2*)(Cl + o0 + (size_t)8 * N) = __halves2half2(l0, l1);
            }
        }
    }
}

// ---------------------------------------------------------------------------
// x (S,B,D) fp32 -> xf (B,S,D) fp16 hi/lo
// ---------------------------------------------------------------------------
__global__ __launch_bounds__(256) void conv_x(const float* __restrict__ x,
                                              __half* __restrict__ xh,
                                              __half* __restrict__ xl) {
    int bs = blockIdx.x;
    int b = bs / S_LEN, s = bs % S_LEN;
    float4 v = ((const float4*)(x + ((size_t)s * BATCH + b) * DIM))[threadIdx.x];
    size_t o = (size_t)bs * DIM + (size_t)threadIdx.x * 4;
    __half h0,l0,h1,l1,h2,l2,h3,l3;
    f2pair(v.x, h0, l0); f2pair(v.y, h1, l1);
    f2pair(v.z, h2, l2); f2pair(v.w, h3, l3);
    ((__half2*)(xh + o))[0] = __halves2half2(h0, h1);
    ((__half2*)(xh + o))[1] = __halves2half2(h2, h3);
    ((__half2*)(xl + o))[0] = __halves2half2(l0, l1);
    ((__half2*)(xl + o))[1] = __halves2half2(l2, l3);
}

// fp32 array -> fp16 hi/lo (vectorized)
__global__ __launch_bounds__(256) void conv_pair(const float* __restrict__ X,
                                                 __half* __restrict__ H,
                                                 __half* __restrict__ L,
                                                 int n4) {
    int i = blockIdx.x * 256 + threadIdx.x;
    if (i >= n4) return;
    float4 v = ((const float4*)X)[i];
    size_t o = (size_t)i * 4;
    __half h0,l0,h1,l1,h2,l2,h3,l3;
    f2pair(v.x, h0, l0); f2pair(v.y, h1, l1);
    f2pair(v.z, h2, l2); f2pair(v.w, h3, l3);
    ((__half2*)(H + o))[0] = __halves2half2(h0, h1);
    ((__half2*)(H + o))[1] = __halves2half2(h2, h3);
    ((__half2*)(L + o))[0] = __halves2half2(l0, l1);
    ((__half2*)(L + o))[1] = __halves2half2(l2, l3);
}

// fp16 RxC -> CxR transpose (per batch z)
__global__ __launch_bounds__(256) void transpose_h(const __half* __restrict__ in,
                                                   __half* __restrict__ out,
                                                   int R, int C) {
    __shared__ __half t[32][33];
    in  += (size_t)blockIdx.z * R * C;
    out += (size_t)blockIdx.z * R * C;
    int c0 = blockIdx.x * 32, r0 = blockIdx.y * 32;
    #pragma unroll
    for (int i = threadIdx.y; i < 32; i += 8)
        t[i][threadIdx.x] = in[(size_t)(r0 + i) * C + c0 + threadIdx.x];
    __syncthreads();
    #pragma unroll
    for (int i = threadIdx.y; i < 32; i += 8)
        out[(size_t)(c0 + i) * R + r0 + threadIdx.x] = t[threadIdx.x][i];
}

// softmax over rows of sc (fp32, len S_LEN) -> fp16 hi/lo probs
__global__ __launch_bounds__(256) void softmax_conv(const float* __restrict__ sc,
                                                    __half* __restrict__ ph,
                                                    __half* __restrict__ pl) {
    const int tid = threadIdx.x;
    const float4* p4 = (const float4*)(sc + (size_t)blockIdx.x * S_LEN);
    __shared__ float red[8];

    float4 a = p4[tid], b = p4[tid + 256];
    float lmax = fmaxf(fmaxf(fmaxf(a.x, a.y), fmaxf(a.z, a.w)),
                       fmaxf(fmaxf(b.x, b.y), fmaxf(b.z, b.w)));
    #pragma unroll
    for (int o = 16; o; o >>= 1) lmax = fmaxf(lmax, __shfl_xor_sync(~0u, lmax, o));
    if ((tid & 31) == 0) red[tid >> 5] = lmax;
    __syncthreads();
    float gmax = red[0];
    #pragma unroll
    for (int w = 1; w < 8; ++w) gmax = fmaxf(gmax, red[w]);
    __syncthreads();

    float e[8];
    e[0] = __expf(a.x - gmax); e[1] = __expf(a.y - gmax);
    e[2] = __expf(a.z - gmax); e[3] = __expf(a.w - gmax);
    e[4] = __expf(b.x - gmax); e[5] = __expf(b.y - gmax);
    e[6] = __expf(b.z - gmax); e[7] = __expf(b.w - gmax);
    float lsum = ((e[0]+e[1]) + (e[2]+e[3])) + ((e[4]+e[5]) + (e[6]+e[7]));
    #pragma unroll
    for (int o = 16; o; o >>= 1) lsum += __shfl_xor_sync(~0u, lsum, o);
    if ((tid & 31) == 0) red[tid >> 5] = lsum;
    __syncthreads();
    float gsum = 0.f;
    #pragma unroll
    for (int w = 0; w < 8; ++w) gsum += red[w];
    float inv = 1.f / gsum;

    size_t o0 = (size_t)blockIdx.x * S_LEN + (size_t)tid * 4;
    #pragma unroll
    for (int half = 0; half < 2; ++half) {
        size_t o = o0 + half * 1024;
        __half h0,l0,h1,l1,h2,l2,h3,l3;
        f2pair(e[half*4+0] * inv, h0, l0);
        f2pair(e[half*4+1] * inv, h1, l1);
        f2pair(e[half*4+2] * inv, h2, l2);
        f2pair(e[half*4+3] * inv, h3, l3);
        ((__half2*)(ph + o))[0] = __halves2half2(h0, h1);
        ((__half2*)(ph + o))[1] = __halves2half2(h2, h3);
        ((__half2*)(pl + o))[0] = __halves2half2(l0, l1);
        ((__half2*)(pl + o))[1] = __halves2half2(l2, l3);
    }
}

// ---------------------------------------------------------------------------
extern "C" void kernel_launch(void* const* d_in, const int* in_sizes, int n_in,
                              void* d_out, int out_size) {
    const float* x  = (const float*)d_in[0];
    const float* Wq = (const float*)d_in[1];
    const float* bq = (const float*)d_in[2];
    const float* Wk = (const float*)d_in[3];
    const float* bk = (const float*)d_in[4];
    const float* Wv = (const float*)d_in[5];
    const float* bv = (const float*)d_in[6];
    float* out = (float*)d_out;

    cudaFuncSetAttribute(gemm_fp16s<2>, cudaFuncAttributeMaxDynamicSharedMemorySize,
                         GEMM_SMEM);
    cudaFuncSetAttribute(gemm_fp16s<3>, cudaFuncAttributeMaxDynamicSharedMemorySize,
                         GEMM_SMEM);

    __half *xh, *xl, *wqh, *wql, *wkh, *wkl, *wvh, *wvl;
    __half *qh, *ql, *kh, *kl, *vh, *vl, *vth, *vtl, *ph, *pl;
    float* sc;
    cudaGetSymbolAddress((void**)&xh, g_xh);   cudaGetSymbolAddress((void**)&xl, g_xl);
    cudaGetSymbolAddress((void**)&wqh, g_wqh); cudaGetSymbolAddress((void**)&wql, g_wql);
    cudaGetSymbolAddress((void**)&wkh, g_wkh); cudaGetSymbolAddress((void**)&wkl, g_wkl);
    cudaGetSymbolAddress((void**)&wvh, g_wvh); cudaGetSymbolAddress((void**)&wvl, g_wvl);
    cudaGetSymbolAddress((void**)&qh, g_qh);   cudaGetSymbolAddress((void**)&ql, g_ql);
    cudaGetSymbolAddress((void**)&kh, g_kh);   cudaGetSymbolAddress((void**)&kl, g_kl);
    cudaGetSymbolAddress((void**)&vh, g_vh);   cudaGetSymbolAddress((void**)&vl, g_vl);
    cudaGetSymbolAddress((void**)&vth, g_vth); cudaGetSymbolAddress((void**)&vtl, g_vtl);
    cudaGetSymbolAddress((void**)&ph, g_ph);   cudaGetSymbolAddress((void**)&pl, g_pl);
    cudaGetSymbolAddress((void**)&sc, g_sc);

    // 1) input conversions (fp16 hi/lo splits)
    conv_x<<<MQKV, 256>>>(x, xh, xl);
    conv_pair<<<DIM * DIM / 4 / 256, 256>>>(Wq, wqh, wql, DIM * DIM / 4);
    conv_pair<<<DIM * DIM / 4 / 256, 256>>>(Wk, wkh, wkl, DIM * DIM / 4);
    conv_pair<<<DIM * DIM / 4 / 256, 256>>>(Wv, wvh, wvl, DIM * DIM / 4);

    // 2) QKV projections: 2-term (hh + lh), residual ~2^-12 -> fine pre-softmax
    {
        dim3 grid(DIM / 128, MQKV / 128, 1);
        gemm_fp16s<2><<<grid, 256, GEMM_SMEM>>>(xh, xl, wqh, nullptr, bq, nullptr, qh, ql,
                                                MQKV, DIM, DIM, 1.f, 0, 0, 0);
        gemm_fp16s<2><<<grid, 256, GEMM_SMEM>>>(xh, xl, wkh, nullptr, bk, nullptr, kh, kl,
                                                MQKV, DIM, DIM, 1.f, 0, 0, 0);
        gemm_fp16s<2><<<grid, 256, GEMM_SMEM>>>(xh, xl, wvh, nullptr, bv, nullptr, vh, vl,
                                                MQKV, DIM, DIM, 1.f, 0, 0, 0);
    }

    // 3) V -> V^T (per batch, [S,D] -> [D,S]) for K-major PV operand
    {
        dim3 grid(DIM / 32, S_LEN / 32, BATCH);
        dim3 blk(32, 8);
        transpose_h<<<grid, blk>>>(vh, vth, S_LEN, DIM);
        transpose_h<<<grid, blk>>>(vl, vtl, S_LEN, DIM);
    }

    // 4) scores = Q K^T / sqrt(D): 3-term (softmax-sensitive)
    {
        dim3 grid(S_LEN / 128, S_LEN / 128, BATCH);
        gemm_fp16s<3><<<grid, 256, GEMM_SMEM>>>(qh, ql, kh, kl, nullptr, sc, nullptr, nullptr,
                                                S_LEN, S_LEN, DIM, 0.03125f,
                                                (size_t)S_LEN * DIM, (size_t)S_LEN * DIM,
                                                (size_t)S_LEN * S_LEN);
    }

    // 5) softmax -> fp16 prob pairs
    softmax_conv<<<BATCH * S_LEN, 256>>>(sc, ph, pl);

    // 6) out = P V: 2-term (probs in [0,1], scale-free residual ~2^-12)
    {
        dim3 grid(DIM / 128, S_LEN / 128, BATCH);
        gemm_fp16s<2><<<grid, 256, GEMM_SMEM>>>(ph, pl, vth, nullptr, nullptr, out, nullptr, nullptr,
                                                S_LEN, DIM, S_LEN, 1.f,
                                                (size_t)S_LEN * S_LEN, (size_t)S_LEN * DIM,
                                                (size_t)S_LEN * DIM);
    }
}

// round 8
// speedup vs baseline: 1.4756x; 1.1224x over previous
#include <cuda_runtime.h>
#include <cuda_fp16.h>
#include <cstdint>
#include <cstddef>

#define S_LEN 2048
#define BATCH 4
#define DIM   1024
#define MQKV  (BATCH * S_LEN)   // 8192

// ---------------------------------------------------------------------------
// scratch (static device globals; no allocation in kernel_launch)
// ---------------------------------------------------------------------------
#define DEVH(name, n) __device__ __align__(256) __half name[n]
DEVH(g_xh,  (size_t)MQKV * DIM);
DEVH(g_xl,  (size_t)MQKV * DIM);
DEVH(g_wqh, (size_t)DIM * DIM);  DEVH(g_wql, (size_t)DIM * DIM);
DEVH(g_wkh, (size_t)DIM * DIM);  DEVH(g_wkl, (size_t)DIM * DIM);
DEVH(g_wvh, (size_t)DIM * DIM);  DEVH(g_wvl, (size_t)DIM * DIM);
DEVH(g_qh,  (size_t)MQKV * DIM); DEVH(g_ql,  (size_t)MQKV * DIM);
DEVH(g_kh,  (size_t)MQKV * DIM); DEVH(g_kl,  (size_t)MQKV * DIM);
DEVH(g_vh,  (size_t)MQKV * DIM); DEVH(g_vl,  (size_t)MQKV * DIM);
DEVH(g_vth, (size_t)MQKV * DIM); DEVH(g_vtl, (size_t)MQKV * DIM);
DEVH(g_ph,  (size_t)BATCH * S_LEN * S_LEN);
DEVH(g_pl,  (size_t)BATCH * S_LEN * S_LEN);
__device__ __align__(256) float g_sc[(size_t)BATCH * S_LEN * S_LEN];

// ---------------------------------------------------------------------------
// PTX helpers — non-'a'-suffix ISA only (cp.async, ldmatrix, mma.sync).
// ---------------------------------------------------------------------------
__device__ __forceinline__ uint32_t smem_to_u32(const void* p) {
    uint32_t a;
    asm("{ .reg .u64 t; cvta.to.shared.u64 t, %1; cvt.u32.u64 %0, t; }"
        : "=r"(a) : "l"(p));
    return a;
}
__device__ __forceinline__ void cp_async16(uint32_t s, const void* g) {
    asm volatile("cp.async.cg.shared.global [%0], [%1], 16;" :: "r"(s), "l"(g));
}
#define CP_COMMIT() asm volatile("cp.async.commit_group;" ::: "memory")
#define CP_WAIT(n)  asm volatile("cp.async.wait_group %0;" :: "n"(n) : "memory")

__device__ __forceinline__ void ldsm_x4(uint32_t* r, uint32_t addr) {
    asm volatile("ldmatrix.sync.aligned.m8n8.x4.shared.b16 {%0,%1,%2,%3}, [%4];"
        : "=r"(r[0]), "=r"(r[1]), "=r"(r[2]), "=r"(r[3]) : "r"(addr));
}
__device__ __forceinline__ void mma16816(float* c, const uint32_t* a,
                                         uint32_t b0, uint32_t b1) {
    asm volatile(
        "mma.sync.aligned.m16n8k16.row.col.f32.f16.f16.f32 "
        "{%0,%1,%2,%3}, {%4,%5,%6,%7}, {%8,%9}, {%0,%1,%2,%3};"
        : "+f"(c[0]), "+f"(c[1]), "+f"(c[2]), "+f"(c[3])
        : "r"(a[0]), "r"(a[1]), "r"(a[2]), "r"(a[3]), "r"(b0), "r"(b1));
}

__device__ __forceinline__ void f2pair(float v, __half& h, __half& l) {
    h = __float2half_rn(v);
    l = __float2half_rn(v - __half2float(h));
}

// up to 3 operand/output sets, selected by blockIdx.z when zsel=1
struct G3 {
    const __half* Bh[3];
    const __half* Bl[3];
    const float*  bias[3];
    float*        Cf[3];
    __half*       Ch[3];
    __half*       Cl[3];
};

// ---------------------------------------------------------------------------
// NT GEMM, fp16 split fp32 emulation on tensor cores.
//   NTERMS=3:  hh + lh + hl   residual ~2^-24 (scores)
//   NTERMS=2:  hh + lh        residual ~2^-12 (proj, PV)
// CTA tile 128x128, 256 threads, 8 warps (2x4) of 64x32 warp tiles, K-chunk 32,
// cp.async double buffer. 2 CTAs/SM (register-lean per-mi operand loads).
// zsel=1: blockIdx.z selects weight/bias/output set (fused QKV).
// zsel=0: blockIdx.z is batch index via strides sA/sB/sC (set 0 used).
// ---------------------------------------------------------------------------
#define ROW_B     80                 // 32 fp16 = 64B data + 16B pad
#define TILE_B    (128 * ROW_B)      // 10240 B
#define SMEM_OF(NT) (2 * (NT) * TILE_B)

template <int NTERMS>
__global__ __launch_bounds__(256, 2)
void gemm_fp16s(const __half* __restrict__ Ah, const __half* __restrict__ Al,
                const G3 args,
                int M, int N, int K, float alpha,
                size_t sA, size_t sB, size_t sC, int zsel)
{
    constexpr int NT = (NTERMS == 3) ? 4 : 3;   // tiles per stage
    const uint32_t STAGE_B = NT * TILE_B;

    extern __shared__ __align__(16) char smem[];
    const uint32_t smem_u = smem_to_u32(smem);

    const int tid  = threadIdx.x;
    const int wid  = tid >> 5, lane = tid & 31;
    const int wm   = wid >> 2;        // 0..1 : warp row (64 rows each)
    const int wn   = wid & 3;         // 0..3 : warp col (32 cols each)
    const int m0   = blockIdx.y * 128;
    const int n0   = blockIdx.x * 128;

    const int    zs = zsel ? (int)blockIdx.z : 0;
    const size_t zb = zsel ? 0 : (size_t)blockIdx.z;

    Ah += sA * zb; Al += sA * zb;
    const __half* Bh = args.Bh[zs] + sB * zb;
    const __half* Bl = (NTERMS == 3) ? args.Bl[zs] + sB * zb : nullptr;
    const float*  bias = args.bias[zs];
    float*        Cf = args.Cf[zs];
    __half*       Ch = args.Ch[zs];
    __half*       Cl = args.Cl[zs];
    const size_t  co = sC * zb;

    // ---- loader: NT tiles x 512 16B-chunks, 2 chunks per thread per tile ----
    const int ci0 = tid;
    auto load_stage = [&](int c, int s) {
        const int k0 = c * 32;
        const uint32_t st = smem_u + s * STAGE_B;
        const __half* gsrc[4] = { Ah, Al, Bh, Bl };
        const int rb[4] = { m0, m0, n0, n0 };
        #pragma unroll
        for (int t = 0; t < NT; ++t) {
            #pragma unroll
            for (int h = 0; h < 2; ++h) {
                int ci  = ci0 + h * 256;
                int row = ci >> 2, col = ci & 3;
                const void* g = gsrc[t] + (size_t)(rb[t] + row) * K + k0 + col * 8;
                cp_async16(st + t * TILE_B + row * ROW_B + col * 16, g);
            }
        }
        CP_COMMIT();
    };

    float acc[4][4][4];
    #pragma unroll
    for (int i = 0; i < 4; ++i)
        #pragma unroll
        for (int j = 0; j < 4; ++j)
            #pragma unroll
            for (int e = 0; e < 4; ++e) acc[i][j][e] = 0.f;

    const int NC = K >> 5;             // K / 32
    load_stage(0, 0);

    for (int c = 0; c < NC; ++c) {
        if (c + 1 < NC) { load_stage(c + 1, (c + 1) & 1); CP_WAIT(1); }
        else            { CP_WAIT(0); }
        __syncthreads();

        const uint32_t st = smem_u + (c & 1) * STAGE_B;
        const uint32_t aoff = (uint32_t)((wm * 64 + (lane & 15)) * ROW_B +
                                         ((lane & 16) ? 16 : 0));
        const uint32_t boff = (uint32_t)((wn * 32 + ((lane & 16) >> 1) + (lane & 7)) * ROW_B +
                                         ((lane & 8) ? 16 : 0));
        #pragma unroll
        for (int kk = 0; kk < 2; ++kk) {    // two k16 steps per chunk
            const uint32_t kb = kk * 32;    // 16 fp16 = 32 B
            uint32_t bhf[2][4], blf[2][4];
            ldsm_x4(bhf[0], st + 2 * TILE_B + boff + kb);
            ldsm_x4(bhf[1], st + 2 * TILE_B + boff + kb + 16 * ROW_B);
            if (NTERMS == 3) {
                ldsm_x4(blf[0], st + 3 * TILE_B + boff + kb);
                ldsm_x4(blf[1], st + 3 * TILE_B + boff + kb + 16 * ROW_B);
            }
            // register-lean: a-fragments loaded per mi (live regs ~110)
            #pragma unroll
            for (int mi = 0; mi < 4; ++mi) {
                uint32_t ahf[4], alf[4];
                ldsm_x4(ahf, st + aoff + kb + mi * (16 * ROW_B));
                ldsm_x4(alf, st + TILE_B + aoff + kb + mi * (16 * ROW_B));
                #pragma unroll
                for (int nf = 0; nf < 4; ++nf) {
                    const int hsel = nf >> 1, p = (nf & 1) * 2;
                    mma16816(acc[mi][nf], ahf, bhf[hsel][p], bhf[hsel][p + 1]); // hh
                }
                #pragma unroll
                for (int nf = 0; nf < 4; ++nf) {
                    const int hsel = nf >> 1, p = (nf & 1) * 2;
                    mma16816(acc[mi][nf], alf, bhf[hsel][p], bhf[hsel][p + 1]); // lh
                }
                if (NTERMS == 3) {
                    #pragma unroll
                    for (int nf = 0; nf < 4; ++nf) {
                        const int hsel = nf >> 1, p = (nf & 1) * 2;
                        mma16816(acc[mi][nf], ahf, blf[hsel][p], blf[hsel][p + 1]); // hl
                    }
                }
            }
        }
        __syncthreads();
    }

    // ---- epilogue ----
    const int r0 = lane >> 2;
    const int c0l = (lane & 3) * 2;
    #pragma unroll
    for (int mi = 0; mi < 4; ++mi) {
        #pragma unroll
        for (int nf = 0; nf < 4; ++nf) {
            const int col  = n0 + wn * 32 + nf * 8 + c0l;
            const int rowA = m0 + wm * 64 + mi * 16 + r0;
            float b0 = 0.f, b1 = 0.f;
            if (bias) { b0 = bias[col]; b1 = bias[col + 1]; }
            float v0 = fmaf(alpha, acc[mi][nf][0], b0);
            float v1 = fmaf(alpha, acc[mi][nf][1], b1);
            float v2 = fmaf(alpha, acc[mi][nf][2], b0);
            float v3 = fmaf(alpha, acc[mi][nf][3], b1);
            if (Cf) {
                float* p0 = Cf + co + (size_t)rowA * N + col;
                *(float2*)p0                     = make_float2(v0, v1);
                *(float2*)(p0 + (size_t)8 * N)   = make_float2(v2, v3);
            }
            if (Ch) {
                size_t o0 = co + (size_t)rowA * N + col;
                __half h0, l0, h1, l1;
                f2pair(v0, h0, l0); f2pair(v1, h1, l1);
                *(__half2*)(Ch + o0) = __halves2half2(h0, h1);
                *(__half2*)(Cl + o0) = __halves2half2(l0, l1);
                f2pair(v2, h0, l0); f2pair(v3, h1, l1);
                *(__half2*)(Ch + o0 + (size_t)8 * N) = __halves2half2(h0, h1);
                *(__half2*)(Cl + o0 + (size_t)8 * N) = __halves2half2(l0, l1);
            }
        }
    }
}

// ---------------------------------------------------------------------------
// x (S,B,D) fp32 -> xf (B,S,D) fp16 hi/lo
// ---------------------------------------------------------------------------
__global__ __launch_bounds__(256) void conv_x(const float* __restrict__ x,
                                              __half* __restrict__ xh,
                                              __half* __restrict__ xl) {
    int bs = blockIdx.x;
    int b = bs / S_LEN, s = bs % S_LEN;
    float4 v = ((const float4*)(x + ((size_t)s * BATCH + b) * DIM))[threadIdx.x];
    size_t o = (size_t)bs * DIM + (size_t)threadIdx.x * 4;
    __half h0,l0,h1,l1,h2,l2,h3,l3;
    f2pair(v.x, h0, l0); f2pair(v.y, h1, l1);
    f2pair(v.z, h2, l2); f2pair(v.w, h3, l3);
    ((__half2*)(xh + o))[0] = __halves2half2(h0, h1);
    ((__half2*)(xh + o))[1] = __halves2half2(h2, h3);
    ((__half2*)(xl + o))[0] = __halves2half2(l0, l1);
    ((__half2*)(xl + o))[1] = __halves2half2(l2, l3);
}

// fp32 array -> fp16 hi/lo (vectorized)
__global__ __launch_bounds__(256) void conv_pair(const float* __restrict__ X,
                                                 __half* __restrict__ H,
                                                 __half* __restrict__ L,
                                                 int n4) {
    int i = blockIdx.x * 256 + threadIdx.x;
    if (i >= n4) return;
    float4 v = ((const float4*)X)[i];
    size_t o = (size_t)i * 4;
    __half h0,l0,h1,l1,h2,l2,h3,l3;
    f2pair(v.x, h0, l0); f2pair(v.y, h1, l1);
    f2pair(v.z, h2, l2); f2pair(v.w, h3, l3);
    ((__half2*)(H + o))[0] = __halves2half2(h0, h1);
    ((__half2*)(H + o))[1] = __halves2half2(h2, h3);
    ((__half2*)(L + o))[0] = __halves2half2(l0, l1);
    ((__half2*)(L + o))[1] = __halves2half2(l2, l3);
}

// fp16 RxC -> CxR transpose (per batch z)
__global__ __launch_bounds__(256) void transpose_h(const __half* __restrict__ in,
                                                   __half* __restrict__ out,
                                                   int R, int C) {
    __shared__ __half t[32][33];
    in  += (size_t)blockIdx.z * R * C;
    out += (size_t)blockIdx.z * R * C;
    int c0 = blockIdx.x * 32, r0 = blockIdx.y * 32;
    #pragma unroll
    for (int i = threadIdx.y; i < 32; i += 8)
        t[i][threadIdx.x] = in[(size_t)(r0 + i) * C + c0 + threadIdx.x];
    __syncthreads();
    #pragma unroll
    for (int i = threadIdx.y; i < 32; i += 8)
        out[(size_t)(c0 + i) * R + r0 + threadIdx.x] = t[threadIdx.x][i];
}

// softmax over rows of sc (fp32, len S_LEN) -> fp16 hi/lo probs
__global__ __launch_bounds__(256) void softmax_conv(const float* __restrict__ sc,
                                                    __half* __restrict__ ph,
                                                    __half* __restrict__ pl) {
    const int tid = threadIdx.x;
    const float4* p4 = (const float4*)(sc + (size_t)blockIdx.x * S_LEN);
    __shared__ float red[8];

    float4 a = p4[tid], b = p4[tid + 256];
    float lmax = fmaxf(fmaxf(fmaxf(a.x, a.y), fmaxf(a.z, a.w)),
                       fmaxf(fmaxf(b.x, b.y), fmaxf(b.z, b.w)));
    #pragma unroll
    for (int o = 16; o; o >>= 1) lmax = fmaxf(lmax, __shfl_xor_sync(~0u, lmax, o));
    if ((tid & 31) == 0) red[tid >> 5] = lmax;
    __syncthreads();
    float gmax = red[0];
    #pragma unroll
    for (int w = 1; w < 8; ++w) gmax = fmaxf(gmax, red[w]);
    __syncthreads();

    float e[8];
    e[0] = __expf(a.x - gmax); e[1] = __expf(a.y - gmax);
    e[2] = __expf(a.z - gmax); e[3] = __expf(a.w - gmax);
    e[4] = __expf(b.x - gmax); e[5] = __expf(b.y - gmax);
    e[6] = __expf(b.z - gmax); e[7] = __expf(b.w - gmax);
    float lsum = ((e[0]+e[1]) + (e[2]+e[3])) + ((e[4]+e[5]) + (e[6]+e[7]));
    #pragma unroll
    for (int o = 16; o; o >>= 1) lsum += __shfl_xor_sync(~0u, lsum, o);
    if ((tid & 31) == 0) red[tid >> 5] = lsum;
    __syncthreads();
    float gsum = 0.f;
    #pragma unroll
    for (int w = 0; w < 8; ++w) gsum += red[w];
    float inv = 1.f / gsum;

    size_t o0 = (size_t)blockIdx.x * S_LEN + (size_t)tid * 4;
    #pragma unroll
    for (int half = 0; half < 2; ++half) {
        size_t o = o0 + half * 1024;
        __half h0,l0,h1,l1,h2,l2,h3,l3;
        f2pair(e[half*4+0] * inv, h0, l0);
        f2pair(e[half*4+1] * inv, h1, l1);
        f2pair(e[half*4+2] * inv, h2, l2);
        f2pair(e[half*4+3] * inv, h3, l3);
        ((__half2*)(ph + o))[0] = __halves2half2(h0, h1);
        ((__half2*)(ph + o))[1] = __halves2half2(h2, h3);
        ((__half2*)(pl + o))[0] = __halves2half2(l0, l1);
        ((__half2*)(pl + o))[1] = __halves2half2(l2, l3);
    }
}

// ---------------------------------------------------------------------------
extern "C" void kernel_launch(void* const* d_in, const int* in_sizes, int n_in,
                              void* d_out, int out_size) {
    const float* x  = (const float*)d_in[0];
    const float* Wq = (const float*)d_in[1];
    const float* bq = (const float*)d_in[2];
    const float* Wk = (const float*)d_in[3];
    const float* bk = (const float*)d_in[4];
    const float* Wv = (const float*)d_in[5];
    const float* bv = (const float*)d_in[6];
    float* out = (float*)d_out;

    cudaFuncSetAttribute(gemm_fp16s<2>, cudaFuncAttributeMaxDynamicSharedMemorySize,
                         SMEM_OF(3));
    cudaFuncSetAttribute(gemm_fp16s<3>, cudaFuncAttributeMaxDynamicSharedMemorySize,
                         SMEM_OF(4));

    __half *xh, *xl, *wqh, *wql, *wkh, *wkl, *wvh, *wvl;
    __half *qh, *ql, *kh, *kl, *vh, *vl, *vth, *vtl, *ph, *pl;
    float* sc;
    cudaGetSymbolAddress((void**)&xh, g_xh);   cudaGetSymbolAddress((void**)&xl, g_xl);
    cudaGetSymbolAddress((void**)&wqh, g_wqh); cudaGetSymbolAddress((void**)&wql, g_wql);
    cudaGetSymbolAddress((void**)&wkh, g_wkh); cudaGetSymbolAddress((void**)&wkl, g_wkl);
    cudaGetSymbolAddress((void**)&wvh, g_wvh); cudaGetSymbolAddress((void**)&wvl, g_wvl);
    cudaGetSymbolAddress((void**)&qh, g_qh);   cudaGetSymbolAddress((void**)&ql, g_ql);
    cudaGetSymbolAddress((void**)&kh, g_kh);   cudaGetSymbolAddress((void**)&kl, g_kl);
    cudaGetSymbolAddress((void**)&vh, g_vh);   cudaGetSymbolAddress((void**)&vl, g_vl);
    cudaGetSymbolAddress((void**)&vth, g_vth); cudaGetSymbolAddress((void**)&vtl, g_vtl);
    cudaGetSymbolAddress((void**)&ph, g_ph);   cudaGetSymbolAddress((void**)&pl, g_pl);
    cudaGetSymbolAddress((void**)&sc, g_sc);

    // 1) input conversions (fp16 hi/lo splits)
    conv_x<<<MQKV, 256>>>(x, xh, xl);
    conv_pair<<<DIM * DIM / 4 / 256, 256>>>(Wq, wqh, wql, DIM * DIM / 4);
    conv_pair<<<DIM * DIM / 4 / 256, 256>>>(Wk, wkh, wkl, DIM * DIM / 4);
    conv_pair<<<DIM * DIM / 4 / 256, 256>>>(Wv, wvh, wvl, DIM * DIM / 4);

    // 2) fused QKV projections (one launch, z selects weight set): 2-term
    {
        G3 a{};
        a.Bh[0] = wqh; a.Bh[1] = wkh; a.Bh[2] = wvh;
        a.bias[0] = bq; a.bias[1] = bk; a.bias[2] = bv;
        a.Ch[0] = qh; a.Ch[1] = kh; a.Ch[2] = vh;
        a.Cl[0] = ql; a.Cl[1] = kl; a.Cl[2] = vl;
        dim3 grid(DIM / 128, MQKV / 128, 3);
        gemm_fp16s<2><<<grid, 256, SMEM_OF(3)>>>(xh, xl, a,
                                                 MQKV, DIM, DIM, 1.f, 0, 0, 0, 1);
    }

    // 3) V -> V^T (per batch, [S,D] -> [D,S]) for K-major PV operand
    {
        dim3 grid(DIM / 32, S_LEN / 32, BATCH);
        dim3 blk(32, 8);
        transpose_h<<<grid, blk>>>(vh, vth, S_LEN, DIM);
        transpose_h<<<grid, blk>>>(vl, vtl, S_LEN, DIM);
    }

    // 4) scores = Q K^T / sqrt(D): 3-term (softmax-sensitive)
    {
        G3 a{};
        a.Bh[0] = kh; a.Bl[0] = kl; a.Cf[0] = sc;
        dim3 grid(S_LEN / 128, S_LEN / 128, BATCH);
        gemm_fp16s<3><<<grid, 256, SMEM_OF(4)>>>(qh, ql, a,
                                                 S_LEN, S_LEN, DIM, 0.03125f,
                                                 (size_t)S_LEN * DIM, (size_t)S_LEN * DIM,
                                                 (size_t)S_LEN * S_LEN, 0);
    }

    // 5) softmax -> fp16 prob pairs
    softmax_conv<<<BATCH * S_LEN, 256>>>(sc, ph, pl);

    // 6) out = P V: 2-term (probs in [0,1])
    {
        G3 a{};
        a.Bh[0] = vth; a.Cf[0] = out;
        dim3 grid(DIM / 128, S_LEN / 128, BATCH);
        gemm_fp16s<2><<<grid, 256, SMEM_OF(3)>>>(ph, pl, a,
                                                 S_LEN, DIM, S_LEN, 1.f,
                                                 (size_t)S_LEN * S_LEN, (size_t)S_LEN * DIM,
                                                 (size_t)S_LEN * DIM, 0);
    }
}

// round 9
// speedup vs baseline: 1.6803x; 1.1387x over previous
#include <cuda_runtime.h>
#include <cuda_fp16.h>
#include <cstdint>
#include <cstddef>

#define S_LEN 2048
#define BATCH 4
#define DIM   1024
#define MQKV  (BATCH * S_LEN)   // 8192

// ---------------------------------------------------------------------------
// scratch (static device globals; no allocation in kernel_launch)
// ---------------------------------------------------------------------------
#define DEVH(name, n) __device__ __align__(256) __half name[n]
DEVH(g_xh,  (size_t)MQKV * DIM);
DEVH(g_xl,  (size_t)MQKV * DIM);
DEVH(g_wqh, (size_t)DIM * DIM);  DEVH(g_wql, (size_t)DIM * DIM);
DEVH(g_wkh, (size_t)DIM * DIM);  DEVH(g_wkl, (size_t)DIM * DIM);
DEVH(g_wvh, (size_t)DIM * DIM);  DEVH(g_wvl, (size_t)DIM * DIM);
DEVH(g_qh,  (size_t)MQKV * DIM); DEVH(g_ql,  (size_t)MQKV * DIM);
DEVH(g_kh,  (size_t)MQKV * DIM); DEVH(g_kl,  (size_t)MQKV * DIM);
DEVH(g_vh,  (size_t)MQKV * DIM);
DEVH(g_vth, (size_t)MQKV * DIM);
DEVH(g_ph,  (size_t)BATCH * S_LEN * S_LEN);
__device__ __align__(256) float g_sc[(size_t)BATCH * S_LEN * S_LEN];

// ---------------------------------------------------------------------------
// PTX helpers — non-'a'-suffix ISA only (cp.async, ldmatrix, mma.sync).
// ---------------------------------------------------------------------------
__device__ __forceinline__ uint32_t smem_to_u32(const void* p) {
    uint32_t a;
    asm("{ .reg .u64 t; cvta.to.shared.u64 t, %1; cvt.u32.u64 %0, t; }"
        : "=r"(a) : "l"(p));
    return a;
}
__device__ __forceinline__ void cp_async16(uint32_t s, const void* g) {
    asm volatile("cp.async.cg.shared.global [%0], [%1], 16;" :: "r"(s), "l"(g));
}
#define CP_COMMIT() asm volatile("cp.async.commit_group;" ::: "memory")
#define CP_WAIT(n)  asm volatile("cp.async.wait_group %0;" :: "n"(n) : "memory")

__device__ __forceinline__ void ldsm_x4(uint32_t* r, uint32_t addr) {
    asm volatile("ldmatrix.sync.aligned.m8n8.x4.shared.b16 {%0,%1,%2,%3}, [%4];"
        : "=r"(r[0]), "=r"(r[1]), "=r"(r[2]), "=r"(r[3]) : "r"(addr));
}
__device__ __forceinline__ void mma16816(float* c, const uint32_t* a,
                                         uint32_t b0, uint32_t b1) {
    asm volatile(
        "mma.sync.aligned.m16n8k16.row.col.f32.f16.f16.f32 "
        "{%0,%1,%2,%3}, {%4,%5,%6,%7}, {%8,%9}, {%0,%1,%2,%3};"
        : "+f"(c[0]), "+f"(c[1]), "+f"(c[2]), "+f"(c[3])
        : "r"(a[0]), "r"(a[1]), "r"(a[2]), "r"(a[3]), "r"(b0), "r"(b1));
}

__device__ __forceinline__ void f2pair(float v, __half& h, __half& l) {
    h = __float2half_rn(v);
    l = __float2half_rn(v - __half2float(h));
}

// up to 3 operand/output sets, selected by blockIdx.z when zsel=1
struct G3 {
    const __half* Bh[3];
    const __half* Bl[3];
    const float*  bias[3];
    float*        Cf[3];
    __half*       Ch[3];
    __half*       Cl[3];
};

// ---------------------------------------------------------------------------
// NT GEMM, fp16 split fp32 emulation on tensor cores.
//   NTERMS=3:  hh + lh + hl   residual ~2^-24 (scores)
//   NTERMS=2:  hh + lh        residual ~2^-12 (proj)
//   NTERMS=1:  hh             residual ~2^-11 (PV: probs in [0,1])
// CTA tile 128x128, 256 threads, 8 warps (2x4) of 64x32 warp tiles, K-chunk 32,
// cp.async double buffer, 2 CTAs/SM.
// ---------------------------------------------------------------------------
#define ROW_B     80                 // 32 fp16 = 64B data + 16B pad
#define TILE_B    (128 * ROW_B)      // 10240 B
#define SMEM_OF(NT) (2 * (NT) * TILE_B)

template <int NTERMS>
__global__ __launch_bounds__(256, 2)
void gemm_fp16s(const __half* __restrict__ Ah, const __half* __restrict__ Al,
                const G3 args,
                int M, int N, int K, float alpha,
                size_t sA, size_t sB, size_t sC, int zsel)
{
    constexpr int NT = (NTERMS == 3) ? 4 : ((NTERMS == 2) ? 3 : 2);
    constexpr uint32_t B_OFF = (NTERMS == 1 ? 1 : 2) * TILE_B;  // Bh tile slot
    const uint32_t STAGE_B = NT * TILE_B;

    extern __shared__ __align__(16) char smem[];
    const uint32_t smem_u = smem_to_u32(smem);

    const int tid  = threadIdx.x;
    const int wid  = tid >> 5, lane = tid & 31;
    const int wm   = wid >> 2;        // 0..1 : warp row (64 rows each)
    const int wn   = wid & 3;         // 0..3 : warp col (32 cols each)
    const int m0   = blockIdx.y * 128;
    const int n0   = blockIdx.x * 128;

    const int    zs = zsel ? (int)blockIdx.z : 0;
    const size_t zb = zsel ? 0 : (size_t)blockIdx.z;

    Ah += sA * zb;
    if (NTERMS >= 2) Al += sA * zb;
    const __half* Bh = args.Bh[zs] + sB * zb;
    const __half* Bl = (NTERMS == 3) ? args.Bl[zs] + sB * zb : nullptr;
    const float*  bias = args.bias[zs];
    float*        Cf = args.Cf[zs];
    __half*       Ch = args.Ch[zs];
    __half*       Cl = args.Cl[zs];
    const size_t  co = sC * zb;

    // ---- loader: NT tiles x 512 16B-chunks, 2 chunks per thread per tile ----
    const int ci0 = tid;
    auto load_stage = [&](int c, int s) {
        const int k0 = c * 32;
        const uint32_t st = smem_u + s * STAGE_B;
        const __half* gsrc[4];
        int rb[4];
        if (NTERMS == 1) { gsrc[0] = Ah; gsrc[1] = Bh;
                           rb[0] = m0;  rb[1] = n0; }
        else             { gsrc[0] = Ah; gsrc[1] = Al; gsrc[2] = Bh; gsrc[3] = Bl;
                           rb[0] = m0;  rb[1] = m0;  rb[2] = n0;  rb[3] = n0; }
        #pragma unroll
        for (int t = 0; t < NT; ++t) {
            #pragma unroll
            for (int h = 0; h < 2; ++h) {
                int ci  = ci0 + h * 256;
                int row = ci >> 2, col = ci & 3;
                const void* g = gsrc[t] + (size_t)(rb[t] + row) * K + k0 + col * 8;
                cp_async16(st + t * TILE_B + row * ROW_B + col * 16, g);
            }
        }
        CP_COMMIT();
    };

    float acc[4][4][4];
    #pragma unroll
    for (int i = 0; i < 4; ++i)
        #pragma unroll
        for (int j = 0; j < 4; ++j)
            #pragma unroll
            for (int e = 0; e < 4; ++e) acc[i][j][e] = 0.f;

    const int NC = K >> 5;             // K / 32
    load_stage(0, 0);

    for (int c = 0; c < NC; ++c) {
        if (c + 1 < NC) { load_stage(c + 1, (c + 1) & 1); CP_WAIT(1); }
        else            { CP_WAIT(0); }
        __syncthreads();

        const uint32_t st = smem_u + (c & 1) * STAGE_B;
        const uint32_t aoff = (uint32_t)((wm * 64 + (lane & 15)) * ROW_B +
                                         ((lane & 16) ? 16 : 0));
        const uint32_t boff = (uint32_t)((wn * 32 + ((lane & 16) >> 1) + (lane & 7)) * ROW_B +
                                         ((lane & 8) ? 16 : 0));
        #pragma unroll
        for (int kk = 0; kk < 2; ++kk) {    // two k16 steps per chunk
            const uint32_t kb = kk * 32;    // 16 fp16 = 32 B
            uint32_t bhf[2][4], blf[2][4];
            ldsm_x4(bhf[0], st + B_OFF + boff + kb);
            ldsm_x4(bhf[1], st + B_OFF + boff + kb + 16 * ROW_B);
            if (NTERMS == 3) {
                ldsm_x4(blf[0], st + 3 * TILE_B + boff + kb);
                ldsm_x4(blf[1], st + 3 * TILE_B + boff + kb + 16 * ROW_B);
            }
            #pragma unroll
            for (int mi = 0; mi < 4; ++mi) {
                uint32_t ahf[4], alf[4];
                ldsm_x4(ahf, st + aoff + kb + mi * (16 * ROW_B));
                if (NTERMS >= 2)
                    ldsm_x4(alf, st + TILE_B + aoff + kb + mi * (16 * ROW_B));
                #pragma unroll
                for (int nf = 0; nf < 4; ++nf) {
                    const int hsel = nf >> 1, p = (nf & 1) * 2;
                    mma16816(acc[mi][nf], ahf, bhf[hsel][p], bhf[hsel][p + 1]); // hh
                }
                if (NTERMS >= 2) {
                    #pragma unroll
                    for (int nf = 0; nf < 4; ++nf) {
                        const int hsel = nf >> 1, p = (nf & 1) * 2;
                        mma16816(acc[mi][nf], alf, bhf[hsel][p], bhf[hsel][p + 1]); // lh
                    }
                }
                if (NTERMS == 3) {
                    #pragma unroll
                    for (int nf = 0; nf < 4; ++nf) {
                        const int hsel = nf >> 1, p = (nf & 1) * 2;
                        mma16816(acc[mi][nf], ahf, blf[hsel][p], blf[hsel][p + 1]); // hl
                    }
                }
            }
        }
        __syncthreads();
    }

    // ---- epilogue ----
    const int r0 = lane >> 2;
    const int c0l = (lane & 3) * 2;
    #pragma unroll
    for (int mi = 0; mi < 4; ++mi) {
        #pragma unroll
        for (int nf = 0; nf < 4; ++nf) {
            const int col  = n0 + wn * 32 + nf * 8 + c0l;
            const int rowA = m0 + wm * 64 + mi * 16 + r0;
            float b0 = 0.f, b1 = 0.f;
            if (bias) { b0 = bias[col]; b1 = bias[col + 1]; }
            float v0 = fmaf(alpha, acc[mi][nf][0], b0);
            float v1 = fmaf(alpha, acc[mi][nf][1], b1);
            float v2 = fmaf(alpha, acc[mi][nf][2], b0);
            float v3 = fmaf(alpha, acc[mi][nf][3], b1);
            if (Cf) {
                float* p0 = Cf + co + (size_t)rowA * N + col;
                *(float2*)p0                     = make_float2(v0, v1);
                *(float2*)(p0 + (size_t)8 * N)   = make_float2(v2, v3);
            }
            if (Ch) {
                size_t o0 = co + (size_t)rowA * N + col;
                __half h0, l0, h1, l1;
                f2pair(v0, h0, l0); f2pair(v1, h1, l1);
                *(__half2*)(Ch + o0) = __halves2half2(h0, h1);
                if (Cl) *(__half2*)(Cl + o0) = __halves2half2(l0, l1);
                f2pair(v2, h0, l0); f2pair(v3, h1, l1);
                *(__half2*)(Ch + o0 + (size_t)8 * N) = __halves2half2(h0, h1);
                if (Cl) *(__half2*)(Cl + o0 + (size_t)8 * N) = __halves2half2(l0, l1);
            }
        }
    }
}

// ---------------------------------------------------------------------------
// x (S,B,D) fp32 -> xf (B,S,D) fp16 hi/lo
// ---------------------------------------------------------------------------
__global__ __launch_bounds__(256) void conv_x(const float* __restrict__ x,
                                              __half* __restrict__ xh,
                                              __half* __restrict__ xl) {
    int bs = blockIdx.x;
    int b = bs / S_LEN, s = bs % S_LEN;
    float4 v = ((const float4*)(x + ((size_t)s * BATCH + b) * DIM))[threadIdx.x];
    size_t o = (size_t)bs * DIM + (size_t)threadIdx.x * 4;
    __half h0,l0,h1,l1,h2,l2,h3,l3;
    f2pair(v.x, h0, l0); f2pair(v.y, h1, l1);
    f2pair(v.z, h2, l2); f2pair(v.w, h3, l3);
    ((__half2*)(xh + o))[0] = __halves2half2(h0, h1);
    ((__half2*)(xh + o))[1] = __halves2half2(h2, h3);
    ((__half2*)(xl + o))[0] = __halves2half2(l0, l1);
    ((__half2*)(xl + o))[1] = __halves2half2(l2, l3);
}

// 3 fp32 arrays -> fp16 hi/lo, z-indexed (one launch for Wq, Wk, Wv)
struct C3 { const float* X[3]; __half* H[3]; __half* L[3]; };
__global__ __launch_bounds__(256) void conv_pair3(const C3 a, int n4) {
    int i = blockIdx.x * 256 + threadIdx.x;
    if (i >= n4) return;
    const int z = blockIdx.z;
    float4 v = ((const float4*)a.X[z])[i];
    size_t o = (size_t)i * 4;
    __half h0,l0,h1,l1,h2,l2,h3,l3;
    f2pair(v.x, h0, l0); f2pair(v.y, h1, l1);
    f2pair(v.z, h2, l2); f2pair(v.w, h3, l3);
    ((__half2*)(a.H[z] + o))[0] = __halves2half2(h0, h1);
    ((__half2*)(a.H[z] + o))[1] = __halves2half2(h2, h3);
    ((__half2*)(a.L[z] + o))[0] = __halves2half2(l0, l1);
    ((__half2*)(a.L[z] + o))[1] = __halves2half2(l2, l3);
}

// fp16 RxC -> CxR transpose (per batch z)
__global__ __launch_bounds__(256) void transpose_h(const __half* __restrict__ in,
                                                   __half* __restrict__ out,
                                                   int R, int C) {
    __shared__ __half t[32][33];
    in  += (size_t)blockIdx.z * R * C;
    out += (size_t)blockIdx.z * R * C;
    int c0 = blockIdx.x * 32, r0 = blockIdx.y * 32;
    #pragma unroll
    for (int i = threadIdx.y; i < 32; i += 8)
        t[i][threadIdx.x] = in[(size_t)(r0 + i) * C + c0 + threadIdx.x];
    __syncthreads();
    #pragma unroll
    for (int i = threadIdx.y; i < 32; i += 8)
        out[(size_t)(c0 + i) * R + r0 + threadIdx.x] = t[threadIdx.x][i];
}

// softmax over rows of sc (fp32, len S_LEN) -> fp16 probs (hi only)
__global__ __launch_bounds__(256) void softmax_conv(const float* __restrict__ sc,
                                                    __half* __restrict__ ph) {
    const int tid = threadIdx.x;
    const float4* p4 = (const float4*)(sc + (size_t)blockIdx.x * S_LEN);
    __shared__ float red[8];

    float4 a = p4[tid], b = p4[tid + 256];
    float lmax = fmaxf(fmaxf(fmaxf(a.x, a.y), fmaxf(a.z, a.w)),
                       fmaxf(fmaxf(b.x, b.y), fmaxf(b.z, b.w)));
    #pragma unroll
    for (int o = 16; o; o >>= 1) lmax = fmaxf(lmax, __shfl_xor_sync(~0u, lmax, o));
    if ((tid & 31) == 0) red[tid >> 5] = lmax;
    __syncthreads();
    float gmax = red[0];
    #pragma unroll
    for (int w = 1; w < 8; ++w) gmax = fmaxf(gmax, red[w]);
    __syncthreads();

    float e[8];
    e[0] = __expf(a.x - gmax); e[1] = __expf(a.y - gmax);
    e[2] = __expf(a.z - gmax); e[3] = __expf(a.w - gmax);
    e[4] = __expf(b.x - gmax); e[5] = __expf(b.y - gmax);
    e[6] = __expf(b.z - gmax); e[7] = __expf(b.w - gmax);
    float lsum = ((e[0]+e[1]) + (e[2]+e[3])) + ((e[4]+e[5]) + (e[6]+e[7]));
    #pragma unroll
    for (int o = 16; o; o >>= 1) lsum += __shfl_xor_sync(~0u, lsum, o);
    if ((tid & 31) == 0) red[tid >> 5] = lsum;
    __syncthreads();
    float gsum = 0.f;
    #pragma unroll
    for (int w = 0; w < 8; ++w) gsum += red[w];
    float inv = 1.f / gsum;

    size_t o0 = (size_t)blockIdx.x * S_LEN + (size_t)tid * 4;
    #pragma unroll
    for (int half = 0; half < 2; ++half) {
        size_t o = o0 + half * 1024;
        ((__half2*)(ph + o))[0] = __halves2half2(__float2half_rn(e[half*4+0] * inv),
                                                 __float2half_rn(e[half*4+1] * inv));
        ((__half2*)(ph + o))[1] = __halves2half2(__float2half_rn(e[half*4+2] * inv),
                                                 __float2half_rn(e[half*4+3] * inv));
    }
}

// ---------------------------------------------------------------------------
extern "C" void kernel_launch(void* const* d_in, const int* in_sizes, int n_in,
                              void* d_out, int out_size) {
    const float* x  = (const float*)d_in[0];
    const float* Wq = (const float*)d_in[1];
    const float* bq = (const float*)d_in[2];
    const float* Wk = (const float*)d_in[3];
    const float* bk = (const float*)d_in[4];
    const float* Wv = (const float*)d_in[5];
    const float* bv = (const float*)d_in[6];
    float* out = (float*)d_out;

    cudaFuncSetAttribute(gemm_fp16s<1>, cudaFuncAttributeMaxDynamicSharedMemorySize,
                         SMEM_OF(2));
    cudaFuncSetAttribute(gemm_fp16s<2>, cudaFuncAttributeMaxDynamicSharedMemorySize,
                         SMEM_OF(3));
    cudaFuncSetAttribute(gemm_fp16s<3>, cudaFuncAttributeMaxDynamicSharedMemorySize,
                         SMEM_OF(4));

    __half *xh, *xl, *wqh, *wql, *wkh, *wkl, *wvh, *wvl;
    __half *qh, *ql, *kh, *kl, *vh, *vth, *ph;
    float* sc;
    cudaGetSymbolAddress((void**)&xh, g_xh);   cudaGetSymbolAddress((void**)&xl, g_xl);
    cudaGetSymbolAddress((void**)&wqh, g_wqh); cudaGetSymbolAddress((void**)&wql, g_wql);
    cudaGetSymbolAddress((void**)&wkh, g_wkh); cudaGetSymbolAddress((void**)&wkl, g_wkl);
    cudaGetSymbolAddress((void**)&wvh, g_wvh); cudaGetSymbolAddress((void**)&wvl, g_wvl);
    cudaGetSymbolAddress((void**)&qh, g_qh);   cudaGetSymbolAddress((void**)&ql, g_ql);
    cudaGetSymbolAddress((void**)&kh, g_kh);   cudaGetSymbolAddress((void**)&kl, g_kl);
    cudaGetSymbolAddress((void**)&vh, g_vh);
    cudaGetSymbolAddress((void**)&vth, g_vth);
    cudaGetSymbolAddress((void**)&ph, g_ph);
    cudaGetSymbolAddress((void**)&sc, g_sc);

    // 1) input conversions (fp16 hi/lo splits)
    conv_x<<<MQKV, 256>>>(x, xh, xl);
    {
        C3 c{};
        c.X[0] = Wq; c.X[1] = Wk; c.X[2] = Wv;
        c.H[0] = wqh; c.H[1] = wkh; c.H[2] = wvh;
        c.L[0] = wql; c.L[1] = wkl; c.L[2] = wvl;
        dim3 grid(DIM * DIM / 4 / 256, 1, 3);
        conv_pair3<<<grid, 256>>>(c, DIM * DIM / 4);
    }

    // 2) fused QKV projections (one launch, z selects weight set): 2-term.
    //    V's low half is never consumed downstream -> Cl[2] = nullptr.
    {
        G3 a{};
        a.Bh[0] = wqh; a.Bh[1] = wkh; a.Bh[2] = wvh;
        a.bias[0] = bq; a.bias[1] = bk; a.bias[2] = bv;
        a.Ch[0] = qh; a.Ch[1] = kh; a.Ch[2] = vh;
        a.Cl[0] = ql; a.Cl[1] = kl; a.Cl[2] = nullptr;
        dim3 grid(DIM / 128, MQKV / 128, 3);
        gemm_fp16s<2><<<grid, 256, SMEM_OF(3)>>>(xh, xl, a,
                                                 MQKV, DIM, DIM, 1.f, 0, 0, 0, 1);
    }

    // 3) V -> V^T (hi only; PV never reads a B-low operand)
    {
        dim3 grid(DIM / 32, S_LEN / 32, BATCH);
        dim3 blk(32, 8);
        transpose_h<<<grid, blk>>>(vh, vth, S_LEN, DIM);
    }

    // 4) scores = Q K^T / sqrt(D): 3-term (softmax-sensitive)
    {
        G3 a{};
        a.Bh[0] = kh; a.Bl[0] = kl; a.Cf[0] = sc;
        dim3 grid(S_LEN / 128, S_LEN / 128, BATCH);
        gemm_fp16s<3><<<grid, 256, SMEM_OF(4)>>>(qh, ql, a,
                                                 S_LEN, S_LEN, DIM, 0.03125f,
                                                 (size_t)S_LEN * DIM, (size_t)S_LEN * DIM,
                                                 (size_t)S_LEN * S_LEN, 0);
    }

    // 5) softmax -> fp16 probs (hi only)
    softmax_conv<<<BATCH * S_LEN, 256>>>(sc, ph);

    // 6) out = P V: 1-term pure fp16 (P in [0,1], residual ~2^-11)
    {
        G3 a{};
        a.Bh[0] = vth; a.Cf[0] = out;
        dim3 grid(DIM / 128, S_LEN / 128, BATCH);
        gemm_fp16s<1><<<grid, 256, SMEM_OF(2)>>>(ph, nullptr, a,
                                                 S_LEN, DIM, S_LEN, 1.f,
                                                 (size_t)S_LEN * S_LEN, (size_t)S_LEN * DIM,
                                                 (size_t)S_LEN * DIM, 0);
    }
}

// round 10
// speedup vs baseline: 1.8589x; 1.1063x over previous
#include <cuda_runtime.h>
#include <cuda_fp16.h>
#include <cstdint>
#include <cstddef>

#define S_LEN 2048
#define BATCH 4
#define DIM   1024
#define MQKV  (BATCH * S_LEN)   // 8192

// ---------------------------------------------------------------------------
// scratch (static device globals; no allocation in kernel_launch)
// ---------------------------------------------------------------------------
#define DEVH(name, n) __device__ __align__(256) __half name[n]
DEVH(g_xh,  (size_t)MQKV * DIM);
DEVH(g_xl,  (size_t)MQKV * DIM);
DEVH(g_wqh, (size_t)DIM * DIM);
DEVH(g_wkh, (size_t)DIM * DIM);
DEVH(g_wvh, (size_t)DIM * DIM);
DEVH(g_qh,  (size_t)MQKV * DIM); DEVH(g_ql,  (size_t)MQKV * DIM);
DEVH(g_kh,  (size_t)MQKV * DIM);
DEVH(g_vh,  (size_t)MQKV * DIM);
DEVH(g_vth, (size_t)MQKV * DIM);
DEVH(g_ph,  (size_t)BATCH * S_LEN * S_LEN);
__device__ __align__(256) float g_sc[(size_t)BATCH * S_LEN * S_LEN];

// ---------------------------------------------------------------------------
// PTX helpers — non-'a'-suffix ISA only (cp.async, ldmatrix, mma.sync).
// ---------------------------------------------------------------------------
__device__ __forceinline__ uint32_t smem_to_u32(const void* p) {
    uint32_t a;
    asm("{ .reg .u64 t; cvta.to.shared.u64 t, %1; cvt.u32.u64 %0, t; }"
        : "=r"(a) : "l"(p));
    return a;
}
__device__ __forceinline__ void cp_async16(uint32_t s, const void* g) {
    asm volatile("cp.async.cg.shared.global [%0], [%1], 16;" :: "r"(s), "l"(g));
}
#define CP_COMMIT() asm volatile("cp.async.commit_group;" ::: "memory")
#define CP_WAIT(n)  asm volatile("cp.async.wait_group %0;" :: "n"(n) : "memory")

__device__ __forceinline__ void ldsm_x4(uint32_t* r, uint32_t addr) {
    asm volatile("ldmatrix.sync.aligned.m8n8.x4.shared.b16 {%0,%1,%2,%3}, [%4];"
        : "=r"(r[0]), "=r"(r[1]), "=r"(r[2]), "=r"(r[3]) : "r"(addr));
}
__device__ __forceinline__ void mma16816(float* c, const uint32_t* a,
                                         uint32_t b0, uint32_t b1) {
    asm volatile(
        "mma.sync.aligned.m16n8k16.row.col.f32.f16.f16.f32 "
        "{%0,%1,%2,%3}, {%4,%5,%6,%7}, {%8,%9}, {%0,%1,%2,%3};"
        : "+f"(c[0]), "+f"(c[1]), "+f"(c[2]), "+f"(c[3])
        : "r"(a[0]), "r"(a[1]), "r"(a[2]), "r"(a[3]), "r"(b0), "r"(b1));
}

__device__ __forceinline__ void f2pair(float v, __half& h, __half& l) {
    h = __float2half_rn(v);
    l = __float2half_rn(v - __half2float(h));
}

// up to 3 operand/output sets, selected by blockIdx.z when zsel=1
struct G3 {
    const __half* Bh[3];
    const float*  bias[3];
    float*        Cf[3];
    __half*       Ch[3];
    __half*       Cl[3];
};

// ---------------------------------------------------------------------------
// NT GEMM, fp16 split fp32 emulation on tensor cores.
//   NTERMS=2:  hh + lh  (A split hi/lo, B hi only)  residual ~2^-12
//   NTERMS=1:  hh       (pure fp16)                 residual ~2^-11
// CTA tile 128x128, 256 threads, 8 warps (2x4) of 64x32 warp tiles, K-chunk 32,
// cp.async double buffer, 2 CTAs/SM.
// ---------------------------------------------------------------------------
#define ROW_B     80                 // 32 fp16 = 64B data + 16B pad
#define TILE_B    (128 * ROW_B)      // 10240 B
#define SMEM_OF(NT) (2 * (NT) * TILE_B)

template <int NTERMS>
__global__ __launch_bounds__(256, 2)
void gemm_fp16s(const __half* __restrict__ Ah, const __half* __restrict__ Al,
                const G3 args,
                int M, int N, int K, float alpha,
                size_t sA, size_t sB, size_t sC, int zsel)
{
    constexpr int NT = (NTERMS == 2) ? 3 : 2;   // tiles per stage
    constexpr uint32_t B_OFF = (NTERMS == 1 ? 1 : 2) * TILE_B;  // Bh tile slot
    const uint32_t STAGE_B = NT * TILE_B;

    extern __shared__ __align__(16) char smem[];
    const uint32_t smem_u = smem_to_u32(smem);

    const int tid  = threadIdx.x;
    const int wid  = tid >> 5, lane = tid & 31;
    const int wm   = wid >> 2;        // 0..1 : warp row (64 rows each)
    const int wn   = wid & 3;         // 0..3 : warp col (32 cols each)
    const int m0   = blockIdx.y * 128;
    const int n0   = blockIdx.x * 128;

    const int    zs = zsel ? (int)blockIdx.z : 0;
    const size_t zb = zsel ? 0 : (size_t)blockIdx.z;

    Ah += sA * zb;
    if (NTERMS >= 2) Al += sA * zb;
    const __half* Bh = args.Bh[zs] + sB * zb;
    const float*  bias = args.bias[zs];
    float*        Cf = args.Cf[zs];
    __half*       Ch = args.Ch[zs];
    __half*       Cl = args.Cl[zs];
    const size_t  co = sC * zb;

    // ---- loader: NT tiles x 512 16B-chunks, 2 chunks per thread per tile ----
    const int ci0 = tid;
    auto load_stage = [&](int c, int s) {
        const int k0 = c * 32;
        const uint32_t st = smem_u + s * STAGE_B;
        const __half* gsrc[3];
        int rb[3];
        if (NTERMS == 1) { gsrc[0] = Ah; gsrc[1] = Bh;
                           rb[0] = m0;  rb[1] = n0; }
        else             { gsrc[0] = Ah; gsrc[1] = Al; gsrc[2] = Bh;
                           rb[0] = m0;  rb[1] = m0;  rb[2] = n0; }
        #pragma unroll
        for (int t = 0; t < NT; ++t) {
            #pragma unroll
            for (int h = 0; h < 2; ++h) {
                int ci  = ci0 + h * 256;
                int row = ci >> 2, col = ci & 3;
                const void* g = gsrc[t] + (size_t)(rb[t] + row) * K + k0 + col * 8;
                cp_async16(st + t * TILE_B + row * ROW_B + col * 16, g);
            }
        }
        CP_COMMIT();
    };

    float acc[4][4][4];
    #pragma unroll
    for (int i = 0; i < 4; ++i)
        #pragma unroll
        for (int j = 0; j < 4; ++j)
            #pragma unroll
            for (int e = 0; e < 4; ++e) acc[i][j][e] = 0.f;

    const int NC = K >> 5;             // K / 32
    load_stage(0, 0);

    for (int c = 0; c < NC; ++c) {
        if (c + 1 < NC) { load_stage(c + 1, (c + 1) & 1); CP_WAIT(1); }
        else            { CP_WAIT(0); }
        __syncthreads();

        const uint32_t st = smem_u + (c & 1) * STAGE_B;
        const uint32_t aoff = (uint32_t)((wm * 64 + (lane & 15)) * ROW_B +
                                         ((lane & 16) ? 16 : 0));
        const uint32_t boff = (uint32_t)((wn * 32 + ((lane & 16) >> 1) + (lane & 7)) * ROW_B +
                                         ((lane & 8) ? 16 : 0));
        #pragma unroll
        for (int kk = 0; kk < 2; ++kk) {    // two k16 steps per chunk
            const uint32_t kb = kk * 32;    // 16 fp16 = 32 B
            uint32_t bhf[2][4];
            ldsm_x4(bhf[0], st + B_OFF + boff + kb);
            ldsm_x4(bhf[1], st + B_OFF + boff + kb + 16 * ROW_B);
            #pragma unroll
            for (int mi = 0; mi < 4; ++mi) {
                uint32_t ahf[4], alf[4];
                ldsm_x4(ahf, st + aoff + kb + mi * (16 * ROW_B));
                if (NTERMS >= 2)
                    ldsm_x4(alf, st + TILE_B + aoff + kb + mi * (16 * ROW_B));
                #pragma unroll
                for (int nf = 0; nf < 4; ++nf) {
                    const int hsel = nf >> 1, p = (nf & 1) * 2;
                    mma16816(acc[mi][nf], ahf, bhf[hsel][p], bhf[hsel][p + 1]); // hh
                }
                if (NTERMS >= 2) {
                    #pragma unroll
                    for (int nf = 0; nf < 4; ++nf) {
                        const int hsel = nf >> 1, p = (nf & 1) * 2;
                        mma16816(acc[mi][nf], alf, bhf[hsel][p], bhf[hsel][p + 1]); // lh
                    }
                }
            }
        }
        __syncthreads();
    }

    // ---- epilogue ----
    const int r0 = lane >> 2;
    const int c0l = (lane & 3) * 2;
    #pragma unroll
    for (int mi = 0; mi < 4; ++mi) {
        #pragma unroll
        for (int nf = 0; nf < 4; ++nf) {
            const int col  = n0 + wn * 32 + nf * 8 + c0l;
            const int rowA = m0 + wm * 64 + mi * 16 + r0;
            float b0 = 0.f, b1 = 0.f;
            if (bias) { b0 = bias[col]; b1 = bias[col + 1]; }
            float v0 = fmaf(alpha, acc[mi][nf][0], b0);
            float v1 = fmaf(alpha, acc[mi][nf][1], b1);
            float v2 = fmaf(alpha, acc[mi][nf][2], b0);
            float v3 = fmaf(alpha, acc[mi][nf][3], b1);
            if (Cf) {
                float* p0 = Cf + co + (size_t)rowA * N + col;
                *(float2*)p0                     = make_float2(v0, v1);
                *(float2*)(p0 + (size_t)8 * N)   = make_float2(v2, v3);
            }
            if (Ch) {
                size_t o0 = co + (size_t)rowA * N + col;
                __half h0, l0, h1, l1;
                f2pair(v0, h0, l0); f2pair(v1, h1, l1);
                *(__half2*)(Ch + o0) = __halves2half2(h0, h1);
                if (Cl) *(__half2*)(Cl + o0) = __halves2half2(l0, l1);
                f2pair(v2, h0, l0); f2pair(v3, h1, l1);
                *(__half2*)(Ch + o0 + (size_t)8 * N) = __halves2half2(h0, h1);
                if (Cl) *(__half2*)(Cl + o0 + (size_t)8 * N) = __halves2half2(l0, l1);
            }
        }
    }
}

// ---------------------------------------------------------------------------
// x (S,B,D) fp32 -> xf (B,S,D) fp16 hi/lo
// ---------------------------------------------------------------------------
__global__ __launch_bounds__(256) void conv_x(const float* __restrict__ x,
                                              __half* __restrict__ xh,
                                              __half* __restrict__ xl) {
    int bs = blockIdx.x;
    int b = bs / S_LEN, s = bs % S_LEN;
    float4 v = ((const float4*)(x + ((size_t)s * BATCH + b) * DIM))[threadIdx.x];
    size_t o = (size_t)bs * DIM + (size_t)threadIdx.x * 4;
    __half h0,l0,h1,l1,h2,l2,h3,l3;
    f2pair(v.x, h0, l0); f2pair(v.y, h1, l1);
    f2pair(v.z, h2, l2); f2pair(v.w, h3, l3);
    ((__half2*)(xh + o))[0] = __halves2half2(h0, h1);
    ((__half2*)(xh + o))[1] = __halves2half2(h2, h3);
    ((__half2*)(xl + o))[0] = __halves2half2(l0, l1);
    ((__half2*)(xl + o))[1] = __halves2half2(l2, l3);
}

// 3 fp32 arrays -> fp16 (hi only; W-low splits are never consumed), z-indexed
struct C3 { const float* X[3]; __half* H[3]; };
__global__ __launch_bounds__(256) void conv_hi3(const C3 a, int n4) {
    int i = blockIdx.x * 256 + threadIdx.x;
    if (i >= n4) return;
    const int z = blockIdx.z;
    float4 v = ((const float4*)a.X[z])[i];
    size_t o = (size_t)i * 4;
    ((__half2*)(a.H[z] + o))[0] = __halves2half2(__float2half_rn(v.x),
                                                 __float2half_rn(v.y));
    ((__half2*)(a.H[z] + o))[1] = __halves2half2(__float2half_rn(v.z),
                                                 __float2half_rn(v.w));
}

// fp16 RxC -> CxR transpose (per batch z)
__global__ __launch_bounds__(256) void transpose_h(const __half* __restrict__ in,
                                                   __half* __restrict__ out,
                                                   int R, int C) {
    __shared__ __half t[32][33];
    in  += (size_t)blockIdx.z * R * C;
    out += (size_t)blockIdx.z * R * C;
    int c0 = blockIdx.x * 32, r0 = blockIdx.y * 32;
    #pragma unroll
    for (int i = threadIdx.y; i < 32; i += 8)
        t[i][threadIdx.x] = in[(size_t)(r0 + i) * C + c0 + threadIdx.x];
    __syncthreads();
    #pragma unroll
    for (int i = threadIdx.y; i < 32; i += 8)
        out[(size_t)(c0 + i) * R + r0 + threadIdx.x] = t[threadIdx.x][i];
}

// softmax over rows of sc (fp32, len S_LEN) -> fp16 probs (hi only)
__global__ __launch_bounds__(256) void softmax_conv(const float* __restrict__ sc,
                                                    __half* __restrict__ ph) {
    const int tid = threadIdx.x;
    const float4* p4 = (const float4*)(sc + (size_t)blockIdx.x * S_LEN);
    __shared__ float red[8];

    float4 a = p4[tid], b = p4[tid + 256];
    float lmax = fmaxf(fmaxf(fmaxf(a.x, a.y), fmaxf(a.z, a.w)),
                       fmaxf(fmaxf(b.x, b.y), fmaxf(b.z, b.w)));
    #pragma unroll
    for (int o = 16; o; o >>= 1) lmax = fmaxf(lmax, __shfl_xor_sync(~0u, lmax, o));
    if ((tid & 31) == 0) red[tid >> 5] = lmax;
    __syncthreads();
    float gmax = red[0];
    #pragma unroll
    for (int w = 1; w < 8; ++w) gmax = fmaxf(gmax, red[w]);
    __syncthreads();

    float e[8];
    e[0] = __expf(a.x - gmax); e[1] = __expf(a.y - gmax);
    e[2] = __expf(a.z - gmax); e[3] = __expf(a.w - gmax);
    e[4] = __expf(b.x - gmax); e[5] = __expf(b.y - gmax);
    e[6] = __expf(b.z - gmax); e[7] = __expf(b.w - gmax);
    float lsum = ((e[0]+e[1]) + (e[2]+e[3])) + ((e[4]+e[5]) + (e[6]+e[7]));
    #pragma unroll
    for (int o = 16; o; o >>= 1) lsum += __shfl_xor_sync(~0u, lsum, o);
    if ((tid & 31) == 0) red[tid >> 5] = lsum;
    __syncthreads();
    float gsum = 0.f;
    #pragma unroll
    for (int w = 0; w < 8; ++w) gsum += red[w];
    float inv = 1.f / gsum;

    size_t o0 = (size_t)blockIdx.x * S_LEN + (size_t)tid * 4;
    #pragma unroll
    for (int half = 0; half < 2; ++half) {
        size_t o = o0 + half * 1024;
        ((__half2*)(ph + o))[0] = __halves2half2(__float2half_rn(e[half*4+0] * inv),
                                                 __float2half_rn(e[half*4+1] * inv));
        ((__half2*)(ph + o))[1] = __halves2half2(__float2half_rn(e[half*4+2] * inv),
                                                 __float2half_rn(e[half*4+3] * inv));
    }
}

// ---------------------------------------------------------------------------
extern "C" void kernel_launch(void* const* d_in, const int* in_sizes, int n_in,
                              void* d_out, int out_size) {
    const float* x  = (const float*)d_in[0];
    const float* Wq = (const float*)d_in[1];
    const float* bq = (const float*)d_in[2];
    const float* Wk = (const float*)d_in[3];
    const float* bk = (const float*)d_in[4];
    const float* Wv = (const float*)d_in[5];
    const float* bv = (const float*)d_in[6];
    float* out = (float*)d_out;

    cudaFuncSetAttribute(gemm_fp16s<1>, cudaFuncAttributeMaxDynamicSharedMemorySize,
                         SMEM_OF(2));
    cudaFuncSetAttribute(gemm_fp16s<2>, cudaFuncAttributeMaxDynamicSharedMemorySize,
                         SMEM_OF(3));

    __half *xh, *xl, *wqh, *wkh, *wvh;
    __half *qh, *ql, *kh, *vh, *vth, *ph;
    float* sc;
    cudaGetSymbolAddress((void**)&xh, g_xh);   cudaGetSymbolAddress((void**)&xl, g_xl);
    cudaGetSymbolAddress((void**)&wqh, g_wqh);
    cudaGetSymbolAddress((void**)&wkh, g_wkh);
    cudaGetSymbolAddress((void**)&wvh, g_wvh);
    cudaGetSymbolAddress((void**)&qh, g_qh);   cudaGetSymbolAddress((void**)&ql, g_ql);
    cudaGetSymbolAddress((void**)&kh, g_kh);
    cudaGetSymbolAddress((void**)&vh, g_vh);
    cudaGetSymbolAddress((void**)&vth, g_vth);
    cudaGetSymbolAddress((void**)&ph, g_ph);
    cudaGetSymbolAddress((void**)&sc, g_sc);

    // 1) input conversions (x: hi/lo split; W: hi only — lows never consumed)
    conv_x<<<MQKV, 256>>>(x, xh, xl);
    {
        C3 c{};
        c.X[0] = Wq; c.X[1] = Wk; c.X[2] = Wv;
        c.H[0] = wqh; c.H[1] = wkh; c.H[2] = wvh;
        dim3 grid(DIM * DIM / 4 / 256, 1, 3);
        conv_hi3<<<grid, 256>>>(c, DIM * DIM / 4);
    }

    // 2) fused QKV projections (one launch, z selects weight set): 2-term.
    //    Only Q needs a low split downstream (scores A-low); K and V hi-only.
    {
        G3 a{};
        a.Bh[0] = wqh; a.Bh[1] = wkh; a.Bh[2] = wvh;
        a.bias[0] = bq; a.bias[1] = bk; a.bias[2] = bv;
        a.Ch[0] = qh; a.Ch[1] = kh; a.Ch[2] = vh;
        a.Cl[0] = ql; a.Cl[1] = nullptr; a.Cl[2] = nullptr;
        dim3 grid(DIM / 128, MQKV / 128, 3);
        gemm_fp16s<2><<<grid, 256, SMEM_OF(3)>>>(xh, xl, a,
                                                 MQKV, DIM, DIM, 1.f, 0, 0, 0, 1);
    }

    // 3) V -> V^T (hi only)
    {
        dim3 grid(DIM / 32, S_LEN / 32, BATCH);
        dim3 blk(32, 8);
        transpose_h<<<grid, blk>>>(vh, vth, S_LEN, DIM);
    }

    // 4) scores = Q K^T / sqrt(D): 2-term (qh+ql vs kh)
    {
        G3 a{};
        a.Bh[0] = kh; a.Cf[0] = sc;
        dim3 grid(S_LEN / 128, S_LEN / 128, BATCH);
        gemm_fp16s<2><<<grid, 256, SMEM_OF(3)>>>(qh, ql, a,
                                                 S_LEN, S_LEN, DIM, 0.03125f,
                                                 (size_t)S_LEN * DIM, (size_t)S_LEN * DIM,
                                                 (size_t)S_LEN * S_LEN, 0);
    }

    // 5) softmax -> fp16 probs (hi only)
    softmax_conv<<<BATCH * S_LEN, 256>>>(sc, ph);

    // 6) out = P V: 1-term pure fp16 (P in [0,1], residual ~2^-11)
    {
        G3 a{};
        a.Bh[0] = vth; a.Cf[0] = out;
        dim3 grid(DIM / 128, S_LEN / 128, BATCH);
        gemm_fp16s<1><<<grid, 256, SMEM_OF(2)>>>(ph, nullptr, a,
                                                 S_LEN, DIM, S_LEN, 1.f,
                                                 (size_t)S_LEN * S_LEN, (size_t)S_LEN * DIM,
                                                 (size_t)S_LEN * DIM, 0);
    }
}

// round 11
// speedup vs baseline: 2.6294x; 1.4145x over previous
#include <cuda_runtime.h>
#include <cuda_fp16.h>
#include <cstdint>
#include <cstddef>

#define S_LEN 2048
#define BATCH 4
#define DIM   1024
#define MQKV  (BATCH * S_LEN)   // 8192

// ---------------------------------------------------------------------------
// scratch (static device globals; no allocation in kernel_launch)
// ---------------------------------------------------------------------------
#define DEVH(name, n) __device__ __align__(256) __half name[n]
DEVH(g_xh,  (size_t)MQKV * DIM);
DEVH(g_wqh, (size_t)DIM * DIM);
DEVH(g_wkh, (size_t)DIM * DIM);
DEVH(g_wvh, (size_t)DIM * DIM);
DEVH(g_qh,  (size_t)MQKV * DIM);
DEVH(g_kh,  (size_t)MQKV * DIM);
DEVH(g_vh,  (size_t)MQKV * DIM);
DEVH(g_vth, (size_t)MQKV * DIM);
DEVH(g_ph,  (size_t)BATCH * S_LEN * S_LEN);
__device__ __align__(256) float g_sc[(size_t)BATCH * S_LEN * S_LEN];

// ---------------------------------------------------------------------------
// PTX helpers — non-'a'-suffix ISA only (cp.async, ldmatrix, mma.sync).
// ---------------------------------------------------------------------------
__device__ __forceinline__ uint32_t smem_to_u32(const void* p) {
    uint32_t a;
    asm("{ .reg .u64 t; cvta.to.shared.u64 t, %1; cvt.u32.u64 %0, t; }"
        : "=r"(a) : "l"(p));
    return a;
}
__device__ __forceinline__ void cp_async16(uint32_t s, const void* g) {
    asm volatile("cp.async.cg.shared.global [%0], [%1], 16;" :: "r"(s), "l"(g));
}
#define CP_COMMIT() asm volatile("cp.async.commit_group;" ::: "memory")
#define CP_WAIT(n)  asm volatile("cp.async.wait_group %0;" :: "n"(n) : "memory")

__device__ __forceinline__ void ldsm_x4(uint32_t* r, uint32_t addr) {
    asm volatile("ldmatrix.sync.aligned.m8n8.x4.shared.b16 {%0,%1,%2,%3}, [%4];"
        : "=r"(r[0]), "=r"(r[1]), "=r"(r[2]), "=r"(r[3]) : "r"(addr));
}
__device__ __forceinline__ void mma16816(float* c, const uint32_t* a,
                                         uint32_t b0, uint32_t b1) {
    asm volatile(
        "mma.sync.aligned.m16n8k16.row.col.f32.f16.f16.f32 "
        "{%0,%1,%2,%3}, {%4,%5,%6,%7}, {%8,%9}, {%0,%1,%2,%3};"
        : "+f"(c[0]), "+f"(c[1]), "+f"(c[2]), "+f"(c[3])
        : "r"(a[0]), "r"(a[1]), "r"(a[2]), "r"(a[3]), "r"(b0), "r"(b1));
}

// up to 3 operand/output sets, selected by blockIdx.z when zsel=1
struct G3 {
    const __half* Bh[3];
    const float*  bias[3];
    float*        Cf[3];
    __half*       Ch[3];
};

// ---------------------------------------------------------------------------
// NT GEMM, pure fp16 inputs, fp32 accumulate, tensor cores.
// CTA tile 128x128, 256 threads, 8 warps (2x4) of 64x32 warp tiles, K-chunk 32,
// cp.async double buffer, 2 CTAs/SM.
// zsel=1: blockIdx.z selects weight/bias/output set (fused QKV).
// zsel=0: blockIdx.z is batch index via strides sA/sB/sC (set 0 used).
// ---------------------------------------------------------------------------
#define ROW_B     80                 // 32 fp16 = 64B data + 16B pad
#define TILE_B    (128 * ROW_B)      // 10240 B
#define STAGE_B   (2 * TILE_B)       // A, B tiles
#define GEMM_SMEM (2 * STAGE_B)      // 40960 B

__global__ __launch_bounds__(256, 2)
void gemm_fp16(const __half* __restrict__ Ah,
               const G3 args,
               int M, int N, int K, float alpha,
               size_t sA, size_t sB, size_t sC, int zsel)
{
    extern __shared__ __align__(16) char smem[];
    const uint32_t smem_u = smem_to_u32(smem);

    const int tid  = threadIdx.x;
    const int wid  = tid >> 5, lane = tid & 31;
    const int wm   = wid >> 2;        // 0..1 : warp row (64 rows each)
    const int wn   = wid & 3;         // 0..3 : warp col (32 cols each)
    const int m0   = blockIdx.y * 128;
    const int n0   = blockIdx.x * 128;

    const int    zs = zsel ? (int)blockIdx.z : 0;
    const size_t zb = zsel ? 0 : (size_t)blockIdx.z;

    Ah += sA * zb;
    const __half* Bh = args.Bh[zs] + sB * zb;
    const float*  bias = args.bias[zs];
    float*        Cf = args.Cf[zs];
    __half*       Ch = args.Ch[zs];
    const size_t  co = sC * zb;

    // ---- loader: 2 tiles x 512 16B-chunks, 2 chunks per thread per tile ----
    const int ci0 = tid;
    auto load_stage = [&](int c, int s) {
        const int k0 = c * 32;
        const uint32_t st = smem_u + s * STAGE_B;
        #pragma unroll
        for (int h = 0; h < 2; ++h) {
            int ci  = ci0 + h * 256;
            int row = ci >> 2, col = ci & 3;
            cp_async16(st + row * ROW_B + col * 16,
                       Ah + (size_t)(m0 + row) * K + k0 + col * 8);
            cp_async16(st + TILE_B + row * ROW_B + col * 16,
                       Bh + (size_t)(n0 + row) * K + k0 + col * 8);
        }
        CP_COMMIT();
    };

    float acc[4][4][4];
    #pragma unroll
    for (int i = 0; i < 4; ++i)
        #pragma unroll
        for (int j = 0; j < 4; ++j)
            #pragma unroll
            for (int e = 0; e < 4; ++e) acc[i][j][e] = 0.f;

    const int NC = K >> 5;             // K / 32
    load_stage(0, 0);

    for (int c = 0; c < NC; ++c) {
        if (c + 1 < NC) { load_stage(c + 1, (c + 1) & 1); CP_WAIT(1); }
        else            { CP_WAIT(0); }
        __syncthreads();

        const uint32_t st = smem_u + (c & 1) * STAGE_B;
        const uint32_t aoff = (uint32_t)((wm * 64 + (lane & 15)) * ROW_B +
                                         ((lane & 16) ? 16 : 0));
        const uint32_t boff = (uint32_t)((wn * 32 + ((lane & 16) >> 1) + (lane & 7)) * ROW_B +
                                         ((lane & 8) ? 16 : 0));
        #pragma unroll
        for (int kk = 0; kk < 2; ++kk) {    // two k16 steps per chunk
            const uint32_t kb = kk * 32;    // 16 fp16 = 32 B
            uint32_t bhf[2][4];
            ldsm_x4(bhf[0], st + TILE_B + boff + kb);
            ldsm_x4(bhf[1], st + TILE_B + boff + kb + 16 * ROW_B);
            #pragma unroll
            for (int mi = 0; mi < 4; ++mi) {
                uint32_t ahf[4];
                ldsm_x4(ahf, st + aoff + kb + mi * (16 * ROW_B));
                #pragma unroll
                for (int nf = 0; nf < 4; ++nf) {
                    const int hsel = nf >> 1, p = (nf & 1) * 2;
                    mma16816(acc[mi][nf], ahf, bhf[hsel][p], bhf[hsel][p + 1]);
                }
            }
        }
        __syncthreads();
    }

    // ---- epilogue ----
    const int r0 = lane >> 2;
    const int c0l = (lane & 3) * 2;
    #pragma unroll
    for (int mi = 0; mi < 4; ++mi) {
        #pragma unroll
        for (int nf = 0; nf < 4; ++nf) {
            const int col  = n0 + wn * 32 + nf * 8 + c0l;
            const int rowA = m0 + wm * 64 + mi * 16 + r0;
            float b0 = 0.f, b1 = 0.f;
            if (bias) { b0 = bias[col]; b1 = bias[col + 1]; }
            float v0 = fmaf(alpha, acc[mi][nf][0], b0);
            float v1 = fmaf(alpha, acc[mi][nf][1], b1);
            float v2 = fmaf(alpha, acc[mi][nf][2], b0);
            float v3 = fmaf(alpha, acc[mi][nf][3], b1);
            if (Cf) {
                float* p0 = Cf + co + (size_t)rowA * N + col;
                *(float2*)p0                     = make_float2(v0, v1);
                *(float2*)(p0 + (size_t)8 * N)   = make_float2(v2, v3);
            }
            if (Ch) {
                size_t o0 = co + (size_t)rowA * N + col;
                *(__half2*)(Ch + o0) =
                    __halves2half2(__float2half_rn(v0), __float2half_rn(v1));
                *(__half2*)(Ch + o0 + (size_t)8 * N) =
                    __halves2half2(__float2half_rn(v2), __float2half_rn(v3));
            }
        }
    }
}

// ---------------------------------------------------------------------------
// x (S,B,D) fp32 -> xf (B,S,D) fp16 (hi only)
// ---------------------------------------------------------------------------
__global__ __launch_bounds__(256) void conv_x(const float* __restrict__ x,
                                              __half* __restrict__ xh) {
    int bs = blockIdx.x;
    int b = bs / S_LEN, s = bs % S_LEN;
    float4 v = ((const float4*)(x + ((size_t)s * BATCH + b) * DIM))[threadIdx.x];
    size_t o = (size_t)bs * DIM + (size_t)threadIdx.x * 4;
    ((__half2*)(xh + o))[0] = __halves2half2(__float2half_rn(v.x),
                                             __float2half_rn(v.y));
    ((__half2*)(xh + o))[1] = __halves2half2(__float2half_rn(v.z),
                                             __float2half_rn(v.w));
}

// 3 fp32 arrays -> fp16, z-indexed (one launch for Wq, Wk, Wv)
struct C3 { const float* X[3]; __half* H[3]; };
__global__ __launch_bounds__(256) void conv_hi3(const C3 a, int n4) {
    int i = blockIdx.x * 256 + threadIdx.x;
    if (i >= n4) return;
    const int z = blockIdx.z;
    float4 v = ((const float4*)a.X[z])[i];
    size_t o = (size_t)i * 4;
    ((__half2*)(a.H[z] + o))[0] = __halves2half2(__float2half_rn(v.x),
                                                 __float2half_rn(v.y));
    ((__half2*)(a.H[z] + o))[1] = __halves2half2(__float2half_rn(v.z),
                                                 __float2half_rn(v.w));
}

// fp16 RxC -> CxR transpose (per batch z)
__global__ __launch_bounds__(256) void transpose_h(const __half* __restrict__ in,
                                                   __half* __restrict__ out,
                                                   int R, int C) {
    __shared__ __half t[32][33];
    in  += (size_t)blockIdx.z * R * C;
    out += (size_t)blockIdx.z * R * C;
    int c0 = blockIdx.x * 32, r0 = blockIdx.y * 32;
    #pragma unroll
    for (int i = threadIdx.y; i < 32; i += 8)
        t[i][threadIdx.x] = in[(size_t)(r0 + i) * C + c0 + threadIdx.x];
    __syncthreads();
    #pragma unroll
    for (int i = threadIdx.y; i < 32; i += 8)
        out[(size_t)(c0 + i) * R + r0 + threadIdx.x] = t[threadIdx.x][i];
}

// softmax over rows of sc (fp32, len S_LEN) -> fp16 probs
__global__ __launch_bounds__(256) void softmax_conv(const float* __restrict__ sc,
                                                    __half* __restrict__ ph) {
    const int tid = threadIdx.x;
    const float4* p4 = (const float4*)(sc + (size_t)blockIdx.x * S_LEN);
    __shared__ float red[8];

    float4 a = p4[tid], b = p4[tid + 256];
    float lmax = fmaxf(fmaxf(fmaxf(a.x, a.y), fmaxf(a.z, a.w)),
                       fmaxf(fmaxf(b.x, b.y), fmaxf(b.z, b.w)));
    #pragma unroll
    for (int o = 16; o; o >>= 1) lmax = fmaxf(lmax, __shfl_xor_sync(~0u, lmax, o));
    if ((tid & 31) == 0) red[tid >> 5] = lmax;
    __syncthreads();
    float gmax = red[0];
    #pragma unroll
    for (int w = 1; w < 8; ++w) gmax = fmaxf(gmax, red[w]);
    __syncthreads();

    float e[8];
    e[0] = __expf(a.x - gmax); e[1] = __expf(a.y - gmax);
    e[2] = __expf(a.z - gmax); e[3] = __expf(a.w - gmax);
    e[4] = __expf(b.x - gmax); e[5] = __expf(b.y - gmax);
    e[6] = __expf(b.z - gmax); e[7] = __expf(b.w - gmax);
    float lsum = ((e[0]+e[1]) + (e[2]+e[3])) + ((e[4]+e[5]) + (e[6]+e[7]));
    #pragma unroll
    for (int o = 16; o; o >>= 1) lsum += __shfl_xor_sync(~0u, lsum, o);
    if ((tid & 31) == 0) red[tid >> 5] = lsum;
    __syncthreads();
    float gsum = 0.f;
    #pragma unroll
    for (int w = 0; w < 8; ++w) gsum += red[w];
    float inv = 1.f / gsum;

    size_t o0 = (size_t)blockIdx.x * S_LEN + (size_t)tid * 4;
    #pragma unroll
    for (int half = 0; half < 2; ++half) {
        size_t o = o0 + half * 1024;
        ((__half2*)(ph + o))[0] = __halves2half2(__float2half_rn(e[half*4+0] * inv),
                                                 __float2half_rn(e[half*4+1] * inv));
        ((__half2*)(ph + o))[1] = __halves2half2(__float2half_rn(e[half*4+2] * inv),
                                                 __float2half_rn(e[half*4+3] * inv));
    }
}

// ---------------------------------------------------------------------------
extern "C" void kernel_launch(void* const* d_in, const int* in_sizes, int n_in,
                              void* d_out, int out_size) {
    const float* x  = (const float*)d_in[0];
    const float* Wq = (const float*)d_in[1];
    const float* bq = (const float*)d_in[2];
    const float* Wk = (const float*)d_in[3];
    const float* bk = (const float*)d_in[4];
    const float* Wv = (const float*)d_in[5];
    const float* bv = (const float*)d_in[6];
    float* out = (float*)d_out;

    cudaFuncSetAttribute(gemm_fp16, cudaFuncAttributeMaxDynamicSharedMemorySize,
                         GEMM_SMEM);

    __half *xh, *wqh, *wkh, *wvh, *qh, *kh, *vh, *vth, *ph;
    float* sc;
    cudaGetSymbolAddress((void**)&xh, g_xh);
    cudaGetSymbolAddress((void**)&wqh, g_wqh);
    cudaGetSymbolAddress((void**)&wkh, g_wkh);
    cudaGetSymbolAddress((void**)&wvh, g_wvh);
    cudaGetSymbolAddress((void**)&qh, g_qh);
    cudaGetSymbolAddress((void**)&kh, g_kh);
    cudaGetSymbolAddress((void**)&vh, g_vh);
    cudaGetSymbolAddress((void**)&vth, g_vth);
    cudaGetSymbolAddress((void**)&ph, g_ph);
    cudaGetSymbolAddress((void**)&sc, g_sc);

    // 1) input conversions (all fp16, no splits)
    conv_x<<<MQKV, 256>>>(x, xh);
    {
        C3 c{};
        c.X[0] = Wq; c.X[1] = Wk; c.X[2] = Wv;
        c.H[0] = wqh; c.H[1] = wkh; c.H[2] = wvh;
        dim3 grid(DIM * DIM / 4 / 256, 1, 3);
        conv_hi3<<<grid, 256>>>(c, DIM * DIM / 4);
    }

    // 2) fused QKV projections (one launch, z selects weight set)
    {
        G3 a{};
        a.Bh[0] = wqh; a.Bh[1] = wkh; a.Bh[2] = wvh;
        a.bias[0] = bq; a.bias[1] = bk; a.bias[2] = bv;
        a.Ch[0] = qh; a.Ch[1] = kh; a.Ch[2] = vh;
        dim3 grid(DIM / 128, MQKV / 128, 3);
        gemm_fp16<<<grid, 256, GEMM_SMEM>>>(xh, a,
                                            MQKV, DIM, DIM, 1.f, 0, 0, 0, 1);
    }

    // 3) V -> V^T (per batch) for K-major PV operand
    {
        dim3 grid(DIM / 32, S_LEN / 32, BATCH);
        dim3 blk(32, 8);
        transpose_h<<<grid, blk>>>(vh, vth, S_LEN, DIM);
    }

    // 4) scores = Q K^T / sqrt(D)
    {
        G3 a{};
        a.Bh[0] = kh; a.Cf[0] = sc;
        dim3 grid(S_LEN / 128, S_LEN / 128, BATCH);
        gemm_fp16<<<grid, 256, GEMM_SMEM>>>(qh, a,
                                            S_LEN, S_LEN, DIM, 0.03125f,
                                            (size_t)S_LEN * DIM, (size_t)S_LEN * DIM,
                                            (size_t)S_LEN * S_LEN, 0);
    }

    // 5) softmax -> fp16 probs
    softmax_conv<<<BATCH * S_LEN, 256>>>(sc, ph);

    // 6) out = P V
    {
        G3 a{};
        a.Bh[0] = vth; a.Cf[0] = out;
        dim3 grid(DIM / 128, S_LEN / 128, BATCH);
        gemm_fp16<<<grid, 256, GEMM_SMEM>>>(ph, a,
                                            S_LEN, DIM, S_LEN, 1.f,
                                            (size_t)S_LEN * S_LEN, (size_t)S_LEN * DIM,
                                            (size_t)S_LEN * DIM, 0);
    }
}

// round 12
// speedup vs baseline: 3.0459x; 1.1584x over previous
#include <cuda_runtime.h>
#include <cuda_fp16.h>
#include <cstdint>
#include <cstddef>

#define S_LEN 2048
#define BATCH 4
#define DIM   1024
#define MQKV  (BATCH * S_LEN)   // 8192

// ---------------------------------------------------------------------------
// scratch (static device globals; no allocation in kernel_launch)
// ---------------------------------------------------------------------------
#define DEVH(name, n) __device__ __align__(256) __half name[n]
DEVH(g_xh,  (size_t)MQKV * DIM);
DEVH(g_wqh, (size_t)DIM * DIM);
DEVH(g_wkh, (size_t)DIM * DIM);
DEVH(g_wvh, (size_t)DIM * DIM);
DEVH(g_qh,  (size_t)MQKV * DIM);
DEVH(g_kh,  (size_t)MQKV * DIM);
DEVH(g_vh,  (size_t)MQKV * DIM);
DEVH(g_ph,  (size_t)BATCH * S_LEN * S_LEN);
__device__ __align__(256) float g_sc[(size_t)BATCH * S_LEN * S_LEN];

// ---------------------------------------------------------------------------
// PTX helpers — non-'a'-suffix ISA only (cp.async, ldmatrix, mma.sync).
// ---------------------------------------------------------------------------
__device__ __forceinline__ uint32_t smem_to_u32(const void* p) {
    uint32_t a;
    asm("{ .reg .u64 t; cvta.to.shared.u64 t, %1; cvt.u32.u64 %0, t; }"
        : "=r"(a) : "l"(p));
    return a;
}
__device__ __forceinline__ void cp_async16(uint32_t s, const void* g) {
    asm volatile("cp.async.cg.shared.global [%0], [%1], 16;" :: "r"(s), "l"(g));
}
#define CP_COMMIT() asm volatile("cp.async.commit_group;" ::: "memory")
#define CP_WAIT(n)  asm volatile("cp.async.wait_group %0;" :: "n"(n) : "memory")

__device__ __forceinline__ void ldsm_x4(uint32_t* r, uint32_t addr) {
    asm volatile("ldmatrix.sync.aligned.m8n8.x4.shared.b16 {%0,%1,%2,%3}, [%4];"
        : "=r"(r[0]), "=r"(r[1]), "=r"(r[2]), "=r"(r[3]) : "r"(addr));
}
__device__ __forceinline__ void ldsm_x4_t(uint32_t* r, uint32_t addr) {
    asm volatile("ldmatrix.sync.aligned.m8n8.x4.trans.shared.b16 {%0,%1,%2,%3}, [%4];"
        : "=r"(r[0]), "=r"(r[1]), "=r"(r[2]), "=r"(r[3]) : "r"(addr));
}
__device__ __forceinline__ void mma16816(float* c, const uint32_t* a,
                                         uint32_t b0, uint32_t b1) {
    asm volatile(
        "mma.sync.aligned.m16n8k16.row.col.f32.f16.f16.f32 "
        "{%0,%1,%2,%3}, {%4,%5,%6,%7}, {%8,%9}, {%0,%1,%2,%3};"
        : "+f"(c[0]), "+f"(c[1]), "+f"(c[2]), "+f"(c[3])
        : "r"(a[0]), "r"(a[1]), "r"(a[2]), "r"(a[3]), "r"(b0), "r"(b1));
}

// up to 3 operand/output sets, selected by blockIdx.z when zsel=1
struct G3 {
    const __half* Bh[3];
    const float*  bias[3];
    float*        Cf[3];
    __half*       Ch[3];
};

// ---------------------------------------------------------------------------
// fp16 GEMM (fp32 accumulate) on tensor cores.
//   TRANSB=0: C[m,n] = sum_k A[m,k] * B[n,k]   (NT; B row-major [n,k])
//   TRANSB=1: C[m,n] = sum_k A[m,k] * B[k,n]   (NN; B row-major [k,n],
//             fragments via ldmatrix.trans — no pre-transpose of B needed)
// CTA tile 128x128, 256 threads, 8 warps (2x4) of 64x32 warp tiles,
// K-chunk 64, cp.async double buffer, 2 CTAs/SM.
// ---------------------------------------------------------------------------
#define ROW_A     144                // 64 fp16 = 128B data + 16B pad
#define TILE_A    (128 * ROW_A)      // 18432 B
#define ROW_BT    272                // 128 fp16 = 256B data + 16B pad (trans B)
#define STAGE_B2  (2 * TILE_A)       // A tile + B tile slot (36864 B)
#define GEMM_SMEM (2 * STAGE_B2)     // 73728 B

template <int TRANSB>
__global__ __launch_bounds__(256, 2)
void gemm_fp16(const __half* __restrict__ Ah,
               const G3 args,
               int M, int N, int K, float alpha,
               size_t sA, size_t sB, size_t sC, int zsel)
{
    extern __shared__ __align__(16) char smem[];
    const uint32_t smem_u = smem_to_u32(smem);

    const int tid  = threadIdx.x;
    const int wid  = tid >> 5, lane = tid & 31;
    const int wm   = wid >> 2;        // 0..1 : warp row (64 rows each)
    const int wn   = wid & 3;         // 0..3 : warp col (32 cols each)
    const int m0   = blockIdx.y * 128;
    const int n0   = blockIdx.x * 128;

    const int    zs = zsel ? (int)blockIdx.z : 0;
    const size_t zb = zsel ? 0 : (size_t)blockIdx.z;

    Ah += sA * zb;
    const __half* Bh = args.Bh[zs] + sB * zb;
    const float*  bias = args.bias[zs];
    float*        Cf = args.Cf[zs];
    __half*       Ch = args.Ch[zs];
    const size_t  co = sC * zb;

    // ---- loader: A tile 128x(64k), B tile (NT: 128x64k | NN: 64k x 128n) ----
    // 1024 16B-chunks per tile, 4 per thread per tile.
    auto load_stage = [&](int c, int s) {
        const int k0 = c * 64;
        const uint32_t st = smem_u + s * STAGE_B2;
        #pragma unroll
        for (int h = 0; h < 4; ++h) {
            int ci = tid + h * 256;
            {   // A: row = m index, 8 chunks per 128B row
                int row = ci >> 3, col = ci & 7;
                cp_async16(st + row * ROW_A + col * 16,
                           Ah + (size_t)(m0 + row) * K + k0 + col * 8);
            }
            if (TRANSB == 0) {   // B row-major [n,k]
                int row = ci >> 3, col = ci & 7;
                cp_async16(st + TILE_A + row * ROW_A + col * 16,
                           Bh + (size_t)(n0 + row) * K + k0 + col * 8);
            } else {             // B row-major [k,n]: 64 rows x 256B
                int row = ci >> 4, col = ci & 15;
                cp_async16(st + TILE_A + row * ROW_BT + col * 16,
                           Bh + (size_t)(k0 + row) * N + n0 + col * 8);
            }
        }
        CP_COMMIT();
    };

    float acc[4][4][4];
    #pragma unroll
    for (int i = 0; i < 4; ++i)
        #pragma unroll
        for (int j = 0; j < 4; ++j)
            #pragma unroll
            for (int e = 0; e < 4; ++e) acc[i][j][e] = 0.f;

    const int NC = K >> 6;             // K / 64
    load_stage(0, 0);

    const uint32_t aoff = (uint32_t)((wm * 64 + (lane & 15)) * ROW_A +
                                     ((lane & 16) ? 16 : 0));
    // NT B fragment addressing (as R10, with ROW_A stride)
    const uint32_t boff_nt = (uint32_t)((wn * 32 + ((lane & 16) >> 1) + (lane & 7)) * ROW_A +
                                        ((lane & 8) ? 16 : 0));
    // NN (trans) B: lanes give k-rows; matrices: (k0-7,n),(k8-15,n),(k0-7,n+8),(k8-15,n+8)
    const uint32_t boff_t = (uint32_t)((((lane >> 3) & 1) * 8 + (lane & 7)) * ROW_BT +
                                       (wn * 32 + (lane >> 4) * 8) * 2);

    for (int c = 0; c < NC; ++c) {
        if (c + 1 < NC) { load_stage(c + 1, (c + 1) & 1); CP_WAIT(1); }
        else            { CP_WAIT(0); }
        __syncthreads();

        const uint32_t st = smem_u + (c & 1) * STAGE_B2;
        #pragma unroll
        for (int kk = 0; kk < 4; ++kk) {    // four k16 steps per chunk
            uint32_t bhf[2][4];
            if (TRANSB == 0) {
                const uint32_t kb = kk * 32;            // 16 fp16 = 32 B
                ldsm_x4(bhf[0], st + TILE_A + boff_nt + kb);
                ldsm_x4(bhf[1], st + TILE_A + boff_nt + kb + 16 * ROW_A);
            } else {
                const uint32_t kb = kk * 16 * ROW_BT;   // 16 k-rows down
                uint32_t r0[4], r1[4];
                ldsm_x4_t(r0, st + TILE_A + boff_t + kb);            // n, n+8
                ldsm_x4_t(r1, st + TILE_A + boff_t + kb + 16 * 2);   // n+16, n+24
                // map to bhf[hsel][p] layout used below:
                bhf[0][0] = r0[0]; bhf[1][0] = r0[1];   // nf=0: b0,b1
                bhf[0][1] = r0[2]; bhf[1][1] = r0[3];   // nf=1
                bhf[0][2] = r1[0]; bhf[1][2] = r1[1];   // nf=2
                bhf[0][3] = r1[2]; bhf[1][3] = r1[3];   // nf=3
            }
            #pragma unroll
            for (int mi = 0; mi < 4; ++mi) {
                uint32_t ahf[4];
                ldsm_x4(ahf, st + aoff + kk * 32 + mi * (16 * ROW_A));
                if (TRANSB == 0) {
                    #pragma unroll
                    for (int nf = 0; nf < 4; ++nf) {
                        const int hsel = nf >> 1, p = (nf & 1) * 2;
                        mma16816(acc[mi][nf], ahf, bhf[hsel][p], bhf[hsel][p + 1]);
                    }
                } else {
                    #pragma unroll
                    for (int nf = 0; nf < 4; ++nf)
                        mma16816(acc[mi][nf], ahf, bhf[0][nf], bhf[1][nf]);
                }
            }
        }
        __syncthreads();
    }

    // ---- epilogue ----
    const int r0 = lane >> 2;
    const int c0l = (lane & 3) * 2;
    #pragma unroll
    for (int mi = 0; mi < 4; ++mi) {
        #pragma unroll
        for (int nf = 0; nf < 4; ++nf) {
            const int col  = n0 + wn * 32 + nf * 8 + c0l;
            const int rowA = m0 + wm * 64 + mi * 16 + r0;
            float b0 = 0.f, b1 = 0.f;
            if (bias) { b0 = bias[col]; b1 = bias[col + 1]; }
            float v0 = fmaf(alpha, acc[mi][nf][0], b0);
            float v1 = fmaf(alpha, acc[mi][nf][1], b1);
            float v2 = fmaf(alpha, acc[mi][nf][2], b0);
            float v3 = fmaf(alpha, acc[mi][nf][3], b1);
            if (Cf) {
                float* p0 = Cf + co + (size_t)rowA * N + col;
                *(float2*)p0                     = make_float2(v0, v1);
                *(float2*)(p0 + (size_t)8 * N)   = make_float2(v2, v3);
            }
            if (Ch) {
                size_t o0 = co + (size_t)rowA * N + col;
                *(__half2*)(Ch + o0) =
                    __halves2half2(__float2half_rn(v0), __float2half_rn(v1));
                *(__half2*)(Ch + o0 + (size_t)8 * N) =
                    __halves2half2(__float2half_rn(v2), __float2half_rn(v3));
            }
        }
    }
}

// ---------------------------------------------------------------------------
// x (S,B,D) fp32 -> xf (B,S,D) fp16
// ---------------------------------------------------------------------------
__global__ __launch_bounds__(256) void conv_x(const float* __restrict__ x,
                                              __half* __restrict__ xh) {
    int bs = blockIdx.x;
    int b = bs / S_LEN, s = bs % S_LEN;
    float4 v = ((const float4*)(x + ((size_t)s * BATCH + b) * DIM))[threadIdx.x];
    size_t o = (size_t)bs * DIM + (size_t)threadIdx.x * 4;
    ((__half2*)(xh + o))[0] = __halves2half2(__float2half_rn(v.x),
                                             __float2half_rn(v.y));
    ((__half2*)(xh + o))[1] = __halves2half2(__float2half_rn(v.z),
                                             __float2half_rn(v.w));
}

// 3 fp32 arrays -> fp16, z-indexed (one launch for Wq, Wk, Wv)
struct C3 { const float* X[3]; __half* H[3]; };
__global__ __launch_bounds__(256) void conv_hi3(const C3 a, int n4) {
    int i = blockIdx.x * 256 + threadIdx.x;
    if (i >= n4) return;
    const int z = blockIdx.z;
    float4 v = ((const float4*)a.X[z])[i];
    size_t o = (size_t)i * 4;
    ((__half2*)(a.H[z] + o))[0] = __halves2half2(__float2half_rn(v.x),
                                                 __float2half_rn(v.y));
    ((__half2*)(a.H[z] + o))[1] = __halves2half2(__float2half_rn(v.z),
                                                 __float2half_rn(v.w));
}

// softmax over rows of sc (fp32, len S_LEN) -> fp16 probs
__global__ __launch_bounds__(256) void softmax_conv(const float* __restrict__ sc,
                                                    __half* __restrict__ ph) {
    const int tid = threadIdx.x;
    const float4* p4 = (const float4*)(sc + (size_t)blockIdx.x * S_LEN);
    __shared__ float red[8];

    float4 a = p4[tid], b = p4[tid + 256];
    float lmax = fmaxf(fmaxf(fmaxf(a.x, a.y), fmaxf(a.z, a.w)),
                       fmaxf(fmaxf(b.x, b.y), fmaxf(b.z, b.w)));
    #pragma unroll
    for (int o = 16; o; o >>= 1) lmax = fmaxf(lmax, __shfl_xor_sync(~0u, lmax, o));
    if ((tid & 31) == 0) red[tid >> 5] = lmax;
    __syncthreads();
    float gmax = red[0];
    #pragma unroll
    for (int w = 1; w < 8; ++w) gmax = fmaxf(gmax, red[w]);
    __syncthreads();

    float e[8];
    e[0] = __expf(a.x - gmax); e[1] = __expf(a.y - gmax);
    e[2] = __expf(a.z - gmax); e[3] = __expf(a.w - gmax);
    e[4] = __expf(b.x - gmax); e[5] = __expf(b.y - gmax);
    e[6] = __expf(b.z - gmax); e[7] = __expf(b.w - gmax);
    float lsum = ((e[0]+e[1]) + (e[2]+e[3])) + ((e[4]+e[5]) + (e[6]+e[7]));
    #pragma unroll
    for (int o = 16; o; o >>= 1) lsum += __shfl_xor_sync(~0u, lsum, o);
    if ((tid & 31) == 0) red[tid >> 5] = lsum;
    __syncthreads();
    float gsum = 0.f;
    #pragma unroll
    for (int w = 0; w < 8; ++w) gsum += red[w];
    float inv = 1.f / gsum;

    size_t o0 = (size_t)blockIdx.x * S_LEN + (size_t)tid * 4;
    #pragma unroll
    for (int half = 0; half < 2; ++half) {
        size_t o = o0 + half * 1024;
        ((__half2*)(ph + o))[0] = __halves2half2(__float2half_rn(e[half*4+0] * inv),
                                                 __float2half_rn(e[half*4+1] * inv));
        ((__half2*)(ph + o))[1] = __halves2half2(__float2half_rn(e[half*4+2] * inv),
                                                 __float2half_rn(e[half*4+3] * inv));
    }
}

// ---------------------------------------------------------------------------
extern "C" void kernel_launch(void* const* d_in, const int* in_sizes, int n_in,
                              void* d_out, int out_size) {
    const float* x  = (const float*)d_in[0];
    const float* Wq = (const float*)d_in[1];
    const float* bq = (const float*)d_in[2];
    const float* Wk = (const float*)d_in[3];
    const float* bk = (const float*)d_in[4];
    const float* Wv = (const float*)d_in[5];
    const float* bv = (const float*)d_in[6];
    float* out = (float*)d_out;

    cudaFuncSetAttribute(gemm_fp16<0>, cudaFuncAttributeMaxDynamicSharedMemorySize,
                         GEMM_SMEM);
    cudaFuncSetAttribute(gemm_fp16<1>, cudaFuncAttributeMaxDynamicSharedMemorySize,
                         GEMM_SMEM);

    __half *xh, *wqh, *wkh, *wvh, *qh, *kh, *vh, *ph;
    float* sc;
    cudaGetSymbolAddress((void**)&xh, g_xh);
    cudaGetSymbolAddress((void**)&wqh, g_wqh);
    cudaGetSymbolAddress((void**)&wkh, g_wkh);
    cudaGetSymbolAddress((void**)&wvh, g_wvh);
    cudaGetSymbolAddress((void**)&qh, g_qh);
    cudaGetSymbolAddress((void**)&kh, g_kh);
    cudaGetSymbolAddress((void**)&vh, g_vh);
    cudaGetSymbolAddress((void**)&ph, g_ph);
    cudaGetSymbolAddress((void**)&sc, g_sc);

    // 1) input conversions
    conv_x<<<MQKV, 256>>>(x, xh);
    {
        C3 c{};
        c.X[0] = Wq; c.X[1] = Wk; c.X[2] = Wv;
        c.H[0] = wqh; c.H[1] = wkh; c.H[2] = wvh;
        dim3 grid(DIM * DIM / 4 / 256, 1, 3);
        conv_hi3<<<grid, 256>>>(c, DIM * DIM / 4);
    }

    // 2) fused QKV projections (NT; one launch, z selects weight set)
    {
        G3 a{};
        a.Bh[0] = wqh; a.Bh[1] = wkh; a.Bh[2] = wvh;
        a.bias[0] = bq; a.bias[1] = bk; a.bias[2] = bv;
        a.Ch[0] = qh; a.Ch[1] = kh; a.Ch[2] = vh;
        dim3 grid(DIM / 128, MQKV / 128, 3);
        gemm_fp16<0><<<grid, 256, GEMM_SMEM>>>(xh, a,
                                               MQKV, DIM, DIM, 1.f, 0, 0, 0, 1);
    }

    // 3) scores = Q K^T / sqrt(D)  (NT)
    {
        G3 a{};
        a.Bh[0] = kh; a.Cf[0] = sc;
        dim3 grid(S_LEN / 128, S_LEN / 128, BATCH);
        gemm_fp16<0><<<grid, 256, GEMM_SMEM>>>(qh, a,
                                               S_LEN, S_LEN, DIM, 0.03125f,
                                               (size_t)S_LEN * DIM, (size_t)S_LEN * DIM,
                                               (size_t)S_LEN * S_LEN, 0);
    }

    // 4) softmax -> fp16 probs
    softmax_conv<<<BATCH * S_LEN, 256>>>(sc, ph);

    // 5) out = P V  (NN via ldmatrix.trans; V used in natural [S,D] layout)
    {
        G3 a{};
        a.Bh[0] = vh; a.Cf[0] = out;
        dim3 grid(DIM / 128, S_LEN / 128, BATCH);
        gemm_fp16<1><<<grid, 256, GEMM_SMEM>>>(ph, a,
                                               S_LEN, DIM, S_LEN, 1.f,
                                               (size_t)S_LEN * S_LEN, (size_t)S_LEN * DIM,
                                               (size_t)S_LEN * DIM, 0);
    }
}

// round 13
// speedup vs baseline: 3.2081x; 1.0533x over previous
#include <cuda_runtime.h>
#include <cuda_fp16.h>
#include <cstdint>
#include <cstddef>

#define S_LEN 2048
#define BATCH 4
#define DIM   1024
#define MQKV  (BATCH * S_LEN)   // 8192

// ---------------------------------------------------------------------------
// scratch (static device globals; no allocation in kernel_launch)
// ---------------------------------------------------------------------------
#define DEVH(name, n) __device__ __align__(256) __half name[n]
DEVH(g_xh,  (size_t)MQKV * DIM);
DEVH(g_wqh, (size_t)DIM * DIM);
DEVH(g_wkh, (size_t)DIM * DIM);
DEVH(g_wvh, (size_t)DIM * DIM);
DEVH(g_qh,  (size_t)MQKV * DIM);
DEVH(g_kh,  (size_t)MQKV * DIM);
DEVH(g_vh,  (size_t)MQKV * DIM);
DEVH(g_ph,  (size_t)BATCH * S_LEN * S_LEN);
__device__ __align__(256) float g_sc[(size_t)BATCH * S_LEN * S_LEN];

// ---------------------------------------------------------------------------
// PTX helpers — non-'a'-suffix ISA only (cp.async, ldmatrix, mma.sync).
// ---------------------------------------------------------------------------
__device__ __forceinline__ uint32_t smem_to_u32(const void* p) {
    uint32_t a;
    asm("{ .reg .u64 t; cvta.to.shared.u64 t, %1; cvt.u32.u64 %0, t; }"
        : "=r"(a) : "l"(p));
    return a;
}
__device__ __forceinline__ void cp_async16(uint32_t s, const void* g) {
    asm volatile("cp.async.cg.shared.global [%0], [%1], 16;" :: "r"(s), "l"(g));
}
#define CP_COMMIT() asm volatile("cp.async.commit_group;" ::: "memory")
#define CP_WAIT(n)  asm volatile("cp.async.wait_group %0;" :: "n"(n) : "memory")

__device__ __forceinline__ void ldsm_x4(uint32_t* r, uint32_t addr) {
    asm volatile("ldmatrix.sync.aligned.m8n8.x4.shared.b16 {%0,%1,%2,%3}, [%4];"
        : "=r"(r[0]), "=r"(r[1]), "=r"(r[2]), "=r"(r[3]) : "r"(addr));
}
__device__ __forceinline__ void ldsm_x4_t(uint32_t* r, uint32_t addr) {
    asm volatile("ldmatrix.sync.aligned.m8n8.x4.trans.shared.b16 {%0,%1,%2,%3}, [%4];"
        : "=r"(r[0]), "=r"(r[1]), "=r"(r[2]), "=r"(r[3]) : "r"(addr));
}
__device__ __forceinline__ void mma16816(float* c, const uint32_t* a,
                                         uint32_t b0, uint32_t b1) {
    asm volatile(
        "mma.sync.aligned.m16n8k16.row.col.f32.f16.f16.f32 "
        "{%0,%1,%2,%3}, {%4,%5,%6,%7}, {%8,%9}, {%0,%1,%2,%3};"
        : "+f"(c[0]), "+f"(c[1]), "+f"(c[2]), "+f"(c[3])
        : "r"(a[0]), "r"(a[1]), "r"(a[2]), "r"(a[3]), "r"(b0), "r"(b1));
}

// up to 3 operand/output sets, selected by blockIdx.z when zsel=1
struct G3 {
    const __half* Bh[3];
    const float*  bias[3];
    float*        Cf[3];
    __half*       Ch[3];
};

// ---------------------------------------------------------------------------
// fp16 GEMM (fp32 accumulate) on tensor cores.
//   TRANSB=0: C[m,n] = sum_k A[m,k] * B[n,k]   (NT; B row-major [n,k])
//   TRANSB=1: C[m,n] = sum_k A[m,k] * B[k,n]   (NN via ldmatrix.trans)
// CTA tile 128x128, 128 threads, 4 warps (2x2) of 64x64 warp tiles,
// K-chunk 64, cp.async double buffer, 2 CTAs/SM.
// Per kk: 8 LDSM for 32 MMAs (vs 6:16 before) — shared port no longer binds.
// ---------------------------------------------------------------------------
#define ROW_A     144                // 64 fp16 = 128B data + 16B pad
#define TILE_A    (128 * ROW_A)      // 18432 B
#define ROW_BT    272                // 128 fp16 = 256B data + 16B pad (trans B)
#define STAGE_B2  (2 * TILE_A)       // A tile + B tile slot (36864 B)
#define GEMM_SMEM (2 * STAGE_B2)     // 73728 B

template <int TRANSB>
__global__ __launch_bounds__(128, 2)
void gemm_fp16(const __half* __restrict__ Ah,
               const G3 args,
               int M, int N, int K, float alpha,
               size_t sA, size_t sB, size_t sC, int zsel)
{
    extern __shared__ __align__(16) char smem[];
    const uint32_t smem_u = smem_to_u32(smem);

    const int tid  = threadIdx.x;
    const int wid  = tid >> 5, lane = tid & 31;
    const int wm   = wid >> 1;        // 0..1 : warp row (64 rows)
    const int wn   = wid & 1;         // 0..1 : warp col (64 cols)
    const int m0   = blockIdx.y * 128;
    const int n0   = blockIdx.x * 128;

    const int    zs = zsel ? (int)blockIdx.z : 0;
    const size_t zb = zsel ? 0 : (size_t)blockIdx.z;

    Ah += sA * zb;
    const __half* Bh = args.Bh[zs] + sB * zb;
    const float*  bias = args.bias[zs];
    float*        Cf = args.Cf[zs];
    __half*       Ch = args.Ch[zs];
    const size_t  co = sC * zb;

    // ---- loader: 1024 16B-chunks per tile, 8 per thread per tile ----
    auto load_stage = [&](int c, int s) {
        const int k0 = c * 64;
        const uint32_t st = smem_u + s * STAGE_B2;
        #pragma unroll
        for (int h = 0; h < 8; ++h) {
            int ci = tid + h * 128;
            {   // A: 128 rows x 8 chunks (128B data per row)
                int row = ci >> 3, col = ci & 7;
                cp_async16(st + row * ROW_A + col * 16,
                           Ah + (size_t)(m0 + row) * K + k0 + col * 8);
            }
            if (TRANSB == 0) {   // B row-major [n,k]: 128 rows x 8 chunks
                int row = ci >> 3, col = ci & 7;
                cp_async16(st + TILE_A + row * ROW_A + col * 16,
                           Bh + (size_t)(n0 + row) * K + k0 + col * 8);
            } else {             // B row-major [k,n]: 64 rows x 16 chunks (256B)
                int row = ci >> 4, col = ci & 15;
                cp_async16(st + TILE_A + row * ROW_BT + col * 16,
                           Bh + (size_t)(k0 + row) * N + n0 + col * 8);
            }
        }
        CP_COMMIT();
    };

    float acc[4][8][4];
    #pragma unroll
    for (int i = 0; i < 4; ++i)
        #pragma unroll
        for (int j = 0; j < 8; ++j)
            #pragma unroll
            for (int e = 0; e < 4; ++e) acc[i][j][e] = 0.f;

    const int NC = K >> 6;             // K / 64
    load_stage(0, 0);

    const uint32_t aoff = (uint32_t)((wm * 64 + (lane & 15)) * ROW_A +
                                     ((lane & 16) ? 16 : 0));
    // NT B: each ldsm_x4 covers 16 n-rows x k16; 4 blocks span 64 n
    const uint32_t boff_nt = (uint32_t)((wn * 64 + ((lane & 16) >> 1) + (lane & 7)) * ROW_A +
                                        ((lane & 8) ? 16 : 0));
    // NN (trans) B: each ldsm_x4_t covers k16 x 16 n; 4 blocks at +32B span 64 n
    const uint32_t boff_t = (uint32_t)((((lane >> 3) & 1) * 8 + (lane & 7)) * ROW_BT +
                                       (wn * 64 + (lane >> 4) * 8) * 2);

    for (int c = 0; c < NC; ++c) {
        if (c + 1 < NC) { load_stage(c + 1, (c + 1) & 1); CP_WAIT(1); }
        else            { CP_WAIT(0); }
        __syncthreads();

        const uint32_t st = smem_u + (c & 1) * STAGE_B2;
        #pragma unroll
        for (int kk = 0; kk < 4; ++kk) {    // four k16 steps per chunk
            uint32_t bhf[4][4];
            if (TRANSB == 0) {
                const uint32_t kb = kk * 32;            // 16 fp16 = 32 B
                #pragma unroll
                for (int j = 0; j < 4; ++j)
                    ldsm_x4(bhf[j], st + TILE_A + boff_nt + kb + j * (16 * ROW_A));
            } else {
                const uint32_t kb = kk * 16 * ROW_BT;   // 16 k-rows down
                #pragma unroll
                for (int j = 0; j < 4; ++j)
                    ldsm_x4_t(bhf[j], st + TILE_A + boff_t + kb + j * 32);
            }
            #pragma unroll
            for (int mi = 0; mi < 4; ++mi) {
                uint32_t ahf[4];
                ldsm_x4(ahf, st + aoff + kk * 32 + mi * (16 * ROW_A));
                if (TRANSB == 0) {
                    #pragma unroll
                    for (int nf = 0; nf < 8; ++nf) {
                        const int j = nf >> 1, p = (nf & 1) * 2;
                        mma16816(acc[mi][nf], ahf, bhf[j][p], bhf[j][p + 1]);
                    }
                } else {
                    #pragma unroll
                    for (int nf = 0; nf < 8; ++nf) {
                        const int j = nf >> 1, p = (nf & 1) * 2;
                        mma16816(acc[mi][nf], ahf, bhf[j][p], bhf[j][p + 1]);
                    }
                }
            }
        }
        __syncthreads();
    }

    // ---- epilogue ----
    const int r0 = lane >> 2;
    const int c0l = (lane & 3) * 2;
    #pragma unroll
    for (int mi = 0; mi < 4; ++mi) {
        #pragma unroll
        for (int nf = 0; nf < 8; ++nf) {
            const int col  = n0 + wn * 64 + nf * 8 + c0l;
            const int rowA = m0 + wm * 64 + mi * 16 + r0;
            float b0 = 0.f, b1 = 0.f;
            if (bias) { b0 = bias[col]; b1 = bias[col + 1]; }
            float v0 = fmaf(alpha, acc[mi][nf][0], b0);
            float v1 = fmaf(alpha, acc[mi][nf][1], b1);
            float v2 = fmaf(alpha, acc[mi][nf][2], b0);
            float v3 = fmaf(alpha, acc[mi][nf][3], b1);
            if (Cf) {
                float* p0 = Cf + co + (size_t)rowA * N + col;
                *(float2*)p0                     = make_float2(v0, v1);
                *(float2*)(p0 + (size_t)8 * N)   = make_float2(v2, v3);
            }
            if (Ch) {
                size_t o0 = co + (size_t)rowA * N + col;
                *(__half2*)(Ch + o0) =
                    __halves2half2(__float2half_rn(v0), __float2half_rn(v1));
                *(__half2*)(Ch + o0 + (size_t)8 * N) =
                    __halves2half2(__float2half_rn(v2), __float2half_rn(v3));
            }
        }
    }
}

// ---------------------------------------------------------------------------
// x (S,B,D) fp32 -> xf (B,S,D) fp16
// ---------------------------------------------------------------------------
__global__ __launch_bounds__(256) void conv_x(const float* __restrict__ x,
                                              __half* __restrict__ xh) {
    int bs = blockIdx.x;
    int b = bs / S_LEN, s = bs % S_LEN;
    float4 v = ((const float4*)(x + ((size_t)s * BATCH + b) * DIM))[threadIdx.x];
    size_t o = (size_t)bs * DIM + (size_t)threadIdx.x * 4;
    ((__half2*)(xh + o))[0] = __halves2half2(__float2half_rn(v.x),
                                             __float2half_rn(v.y));
    ((__half2*)(xh + o))[1] = __halves2half2(__float2half_rn(v.z),
                                             __float2half_rn(v.w));
}

// 3 fp32 arrays -> fp16, z-indexed (one launch for Wq, Wk, Wv)
struct C3 { const float* X[3]; __half* H[3]; };
__global__ __launch_bounds__(256) void conv_hi3(const C3 a, int n4) {
    int i = blockIdx.x * 256 + threadIdx.x;
    if (i >= n4) return;
    const int z = blockIdx.z;
    float4 v = ((const float4*)a.X[z])[i];
    size_t o = (size_t)i * 4;
    ((__half2*)(a.H[z] + o))[0] = __halves2half2(__float2half_rn(v.x),
                                                 __float2half_rn(v.y));
    ((__half2*)(a.H[z] + o))[1] = __halves2half2(__float2half_rn(v.z),
                                                 __float2half_rn(v.w));
}

// softmax over rows of sc (fp32, len S_LEN) -> fp16 probs
__global__ __launch_bounds__(256) void softmax_conv(const float* __restrict__ sc,
                                                    __half* __restrict__ ph) {
    const int tid = threadIdx.x;
    const float4* p4 = (const float4*)(sc + (size_t)blockIdx.x * S_LEN);
    __shared__ float red[8];

    float4 a = p4[tid], b = p4[tid + 256];
    float lmax = fmaxf(fmaxf(fmaxf(a.x, a.y), fmaxf(a.z, a.w)),
                       fmaxf(fmaxf(b.x, b.y), fmaxf(b.z, b.w)));
    #pragma unroll
    for (int o = 16; o; o >>= 1) lmax = fmaxf(lmax, __shfl_xor_sync(~0u, lmax, o));
    if ((tid & 31) == 0) red[tid >> 5] = lmax;
    __syncthreads();
    float gmax = red[0];
    #pragma unroll
    for (int w = 1; w < 8; ++w) gmax = fmaxf(gmax, red[w]);
    __syncthreads();

    float e[8];
    e[0] = __expf(a.x - gmax); e[1] = __expf(a.y - gmax);
    e[2] = __expf(a.z - gmax); e[3] = __expf(a.w - gmax);
    e[4] = __expf(b.x - gmax); e[5] = __expf(b.y - gmax);
    e[6] = __expf(b.z - gmax); e[7] = __expf(b.w - gmax);
    float lsum = ((e[0]+e[1]) + (e[2]+e[3])) + ((e[4]+e[5]) + (e[6]+e[7]));
    #pragma unroll
    for (int o = 16; o; o >>= 1) lsum += __shfl_xor_sync(~0u, lsum, o);
    if ((tid & 31) == 0) red[tid >> 5] = lsum;
    __syncthreads();
    float gsum = 0.f;
    #pragma unroll
    for (int w = 0; w < 8; ++w) gsum += red[w];
    float inv = 1.f / gsum;

    size_t o0 = (size_t)blockIdx.x * S_LEN + (size_t)tid * 4;
    #pragma unroll
    for (int half = 0; half < 2; ++half) {
        size_t o = o0 + half * 1024;
        ((__half2*)(ph + o))[0] = __halves2half2(__float2half_rn(e[half*4+0] * inv),
                                                 __float2half_rn(e[half*4+1] * inv));
        ((__half2*)(ph + o))[1] = __halves2half2(__float2half_rn(e[half*4+2] * inv),
                                                 __float2half_rn(e[half*4+3] * inv));
    }
}

// ---------------------------------------------------------------------------
extern "C" void kernel_launch(void* const* d_in, const int* in_sizes, int n_in,
                              void* d_out, int out_size) {
    const float* x  = (const float*)d_in[0];
    const float* Wq = (const float*)d_in[1];
    const float* bq = (const float*)d_in[2];
    const float* Wk = (const float*)d_in[3];
    const float* bk = (const float*)d_in[4];
    const float* Wv = (const float*)d_in[5];
    const float* bv = (const float*)d_in[6];
    float* out = (float*)d_out;

    cudaFuncSetAttribute(gemm_fp16<0>, cudaFuncAttributeMaxDynamicSharedMemorySize,
                         GEMM_SMEM);
    cudaFuncSetAttribute(gemm_fp16<1>, cudaFuncAttributeMaxDynamicSharedMemorySize,
                         GEMM_SMEM);

    __half *xh, *wqh, *wkh, *wvh, *qh, *kh, *vh, *ph;
    float* sc;
    cudaGetSymbolAddress((void**)&xh, g_xh);
    cudaGetSymbolAddress((void**)&wqh, g_wqh);
    cudaGetSymbolAddress((void**)&wkh, g_wkh);
    cudaGetSymbolAddress((void**)&wvh, g_wvh);
    cudaGetSymbolAddress((void**)&qh, g_qh);
    cudaGetSymbolAddress((void**)&kh, g_kh);
    cudaGetSymbolAddress((void**)&vh, g_vh);
    cudaGetSymbolAddress((void**)&ph, g_ph);
    cudaGetSymbolAddress((void**)&sc, g_sc);

    // 1) input conversions
    conv_x<<<MQKV, 256>>>(x, xh);
    {
        C3 c{};
        c.X[0] = Wq; c.X[1] = Wk; c.X[2] = Wv;
        c.H[0] = wqh; c.H[1] = wkh; c.H[2] = wvh;
        dim3 grid(DIM * DIM / 4 / 256, 1, 3);
        conv_hi3<<<grid, 256>>>(c, DIM * DIM / 4);
    }

    // 2) fused QKV projections (NT; one launch, z selects weight set)
    {
        G3 a{};
        a.Bh[0] = wqh; a.Bh[1] = wkh; a.Bh[2] = wvh;
        a.bias[0] = bq; a.bias[1] = bk; a.bias[2] = bv;
        a.Ch[0] = qh; a.Ch[1] = kh; a.Ch[2] = vh;
        dim3 grid(DIM / 128, MQKV / 128, 3);
        gemm_fp16<0><<<grid, 128, GEMM_SMEM>>>(xh, a,
                                               MQKV, DIM, DIM, 1.f, 0, 0, 0, 1);
    }

    // 3) scores = Q K^T / sqrt(D)  (NT)
    {
        G3 a{};
        a.Bh[0] = kh; a.Cf[0] = sc;
        dim3 grid(S_LEN / 128, S_LEN / 128, BATCH);
        gemm_fp16<0><<<grid, 128, GEMM_SMEM>>>(qh, a,
                                               S_LEN, S_LEN, DIM, 0.03125f,
                                               (size_t)S_LEN * DIM, (size_t)S_LEN * DIM,
                                               (size_t)S_LEN * S_LEN, 0);
    }

    // 4) softmax -> fp16 probs
    softmax_conv<<<BATCH * S_LEN, 256>>>(sc, ph);

    // 5) out = P V  (NN via ldmatrix.trans; V used in natural [S,D] layout)
    {
        G3 a{};
        a.Bh[0] = vh; a.Cf[0] = out;
        dim3 grid(DIM / 128, S_LEN / 128, BATCH);
        gemm_fp16<1><<<grid, 128, GEMM_SMEM>>>(ph, a,
                                               S_LEN, DIM, S_LEN, 1.f,
                                               (size_t)S_LEN * S_LEN, (size_t)S_LEN * DIM,
                                               (size_t)S_LEN * DIM, 0);
    }
}